// round 10
// baseline (speedup 1.0000x reference)
#include <cuda_runtime.h>
#include <cstdint>
#include <cstdio>

// ---------------- problem constants ----------------
#define BB   2
#define DD   32
#define HH   56
#define WW   56
#define CC   96
#define HEADS 3
#define HD   32
#define NN   98          // window tokens = 2*7*7
#define NWIN 1024        // windows per batch = 16*8*8
#define BW   (BB*NWIN)   // 2048 windows
#define TT   (BW*NN)     // 200704 tokens
#define HID  384

// ---------------- scratch (device globals; allocation-free) ----------------
__device__ float g_xw  [(size_t)TT*CC];     // LN1 out (tf32-rounded)
__device__ float g_qkv [(size_t)TT*3*CC];
__device__ float g_ao  [(size_t)TT*CC];     // attn out (tf32-rounded)
__device__ float g_x1  [(size_t)TT*CC];
__device__ float g_h2  [(size_t)TT*CC];     // LN2 out (tf32-rounded)
__device__ float g_hid [(size_t)TT*HID];    // gelu out (tf32-rounded)

// rounded weights: qkv | proj | fc1 | fc2
#define WQKV_OFF 0
#define WPROJ_OFF 27648
#define WFC1_OFF 36864
#define WFC2_OFF 73728
#define WTOT     110592
__device__ float g_wr[WTOT];

__device__ __forceinline__ uint32_t cvt_tf32(float x) {
    uint32_t r;
    asm("cvt.rna.tf32.f32 %0, %1;" : "=r"(r) : "f"(x));
    return r;
}
__device__ __forceinline__ float round_tf32(float x) {
    return __uint_as_float(cvt_tf32(x));
}

// Map window-token index -> spatial token index.
__device__ __forceinline__ int win_to_spatial(int t) {
    int win = t / NN, n = t - win * NN;
    int b  = win >> 10;
    int wi = win & 1023;
    int d0 = wi >> 6, h0 = (wi >> 3) & 7, w0 = wi & 7;
    int dd = n / 49;  int r = n - dd * 49;
    int hh = r / 7;   int ww = r - hh * 7;
    int d = d0 * 2 + dd + 1; if (d >= DD) d -= DD;
    int h = h0 * 7 + hh + 3; if (h >= HH) h -= HH;
    int w = w0 * 7 + ww + 3; if (w >= WW) w -= WW;
    return ((b * DD + d) * HH + h) * WW + w;
}

// ---------------- weight rounding (one-shot, tiny) ----------------
__global__ void round_weights_kernel(const float* __restrict__ qkv_w,
                                     const float* __restrict__ proj_w,
                                     const float* __restrict__ fc1_w,
                                     const float* __restrict__ fc2_w,
                                     float* __restrict__ wr) {
    int i = blockIdx.x * 256 + threadIdx.x;
    if (i < WTOT) {
        float v;
        if      (i < WPROJ_OFF) v = qkv_w[i - WQKV_OFF];
        else if (i < WFC1_OFF)  v = proj_w[i - WPROJ_OFF];
        else if (i < WFC2_OFF)  v = fc1_w[i - WFC1_OFF];
        else                    v = fc2_w[i - WFC2_OFF];
        wr[i] = round_tf32(v);
    }
}

// ---------------- LayerNorm (warp per token, C=96=3*32), tf32-rounded out ----
__global__ void ln_kernel(const float* __restrict__ in,
                          const float* __restrict__ g,
                          const float* __restrict__ bta,
                          float* __restrict__ out, int gather) {
    int t = blockIdx.x * 4 + (threadIdx.x >> 5);
    int lane = threadIdx.x & 31;
    size_t src = gather ? (size_t)win_to_spatial(t) * CC : (size_t)t * CC;
    float x0 = in[src + lane];
    float x1 = in[src + lane + 32];
    float x2 = in[src + lane + 64];
    float s  = x0 + x1 + x2;
    float sq = x0 * x0 + x1 * x1 + x2 * x2;
    #pragma unroll
    for (int o = 16; o; o >>= 1) {
        s  += __shfl_xor_sync(0xffffffffu, s,  o);
        sq += __shfl_xor_sync(0xffffffffu, sq, o);
    }
    float mean = s * (1.0f / 96.0f);
    float var  = sq * (1.0f / 96.0f) - mean * mean;
    float rst  = rsqrtf(var + 1e-5f);
    size_t dst = (size_t)t * CC;
    out[dst + lane]      = round_tf32((x0 - mean) * rst * g[lane]      + bta[lane]);
    out[dst + lane + 32] = round_tf32((x1 - mean) * rst * g[lane + 32] + bta[lane + 32]);
    out[dst + lane + 64] = round_tf32((x2 - mean) * rst * g[lane + 64] + bta[lane + 64]);
}

// ---------------- shared mma helper ----------------
__device__ __forceinline__ void mma_tf32(float* d, const uint32_t* a, const uint32_t* b) {
    asm volatile(
        "mma.sync.aligned.m16n8k8.row.col.f32.tf32.tf32.f32 "
        "{%0,%1,%2,%3}, {%4,%5,%6,%7}, {%8,%9}, {%0,%1,%2,%3};\n"
        : "+f"(d[0]), "+f"(d[1]), "+f"(d[2]), "+f"(d[3])
        : "r"(a[0]), "r"(a[1]), "r"(a[2]), "r"(a[3]),
          "r"(b[0]), "r"(b[1]));
}

// ---------------- tf32 tensor-core GEMM: C[M,Nd] = A[M,K] * W[Nd,K]^T + bias ----
#define GBM 128
#define GBN 64
#define GBK 32
#define SSTR 36

__device__ __forceinline__ void cp16(uint32_t dst_smem, const float* src, bool pred) {
    int sz = pred ? 16 : 0;
    asm volatile("cp.async.ca.shared.global [%0], [%1], 16, %2;\n"
                 :: "r"(dst_smem), "l"(src), "r"(sz));
}

template<int EPI>
__global__ void __launch_bounds__(256)
gemm_kernel(const float* __restrict__ A, const float* __restrict__ Wt,
            const float* __restrict__ bias, float* __restrict__ Cout,
            const float* __restrict__ res, int M, int Nd, int K) {
    __shared__ float As[2][GBM * SSTR];
    __shared__ float Bs[2][GBN * SSTR];

    int tid  = threadIdx.x;
    int lane = tid & 31, warp = tid >> 5;
    int wm = warp >> 1;
    int wn = warp & 1;
    int g  = lane >> 2, l4 = lane & 3;
    int mBase = blockIdx.y * GBM;
    int nBase = blockIdx.x * GBN;

    int lr = tid >> 3;
    int lc = (tid & 7) * 4;

    const float* Ap = A + (size_t)(mBase + lr) * K + lc;
    const float* Bp = Wt + (size_t)(nBase + lr) * K + lc;

    uint32_t asb = (uint32_t)__cvta_generic_to_shared(&As[0][0]);
    uint32_t bsb = (uint32_t)__cvta_generic_to_shared(&Bs[0][0]);

    float acc[2][4][4];
    #pragma unroll
    for (int mt = 0; mt < 2; mt++)
        #pragma unroll
        for (int nt = 0; nt < 4; nt++)
            #pragma unroll
            for (int e = 0; e < 4; e++) acc[mt][nt][e] = 0.0f;

    int nTiles = K / GBK;

    auto prefetch = [&](int s, int kt) {
        uint32_t ad = asb + (uint32_t)(s * GBM * SSTR + lr * SSTR + lc) * 4;
        uint32_t bd = bsb + (uint32_t)(s * GBN * SSTR + lr * SSTR + lc) * 4;
        int kb = kt * GBK;
        #pragma unroll
        for (int i = 0; i < 4; i++)
            cp16(ad + i * 32 * SSTR * 4, Ap + (size_t)i * 32 * K + kb, true);
        #pragma unroll
        for (int i = 0; i < 2; i++)
            cp16(bd + i * 32 * SSTR * 4, Bp + (size_t)i * 32 * K + kb,
                 (nBase + lr + i * 32) < Nd);
        asm volatile("cp.async.commit_group;\n" ::);
    };

    prefetch(0, 0);
    prefetch(1, 1);

    for (int kt = 0; kt < nTiles; kt++) {
        if (kt + 1 < nTiles)
            asm volatile("cp.async.wait_group 1;\n" ::);
        else
            asm volatile("cp.async.wait_group 0;\n" ::);
        __syncthreads();

        int s = kt & 1;
        const float* as = As[s];
        const float* bs = Bs[s];

        #pragma unroll
        for (int kk = 0; kk < GBK; kk += 8) {
            int kq = kk + l4;
            uint32_t af[2][4], bf[4][2];
            #pragma unroll
            for (int mt = 0; mt < 2; mt++) {
                int r = wm * 32 + mt * 16 + g;
                af[mt][0] = __float_as_uint(as[r * SSTR + kq]);
                af[mt][1] = __float_as_uint(as[(r + 8) * SSTR + kq]);
                af[mt][2] = __float_as_uint(as[r * SSTR + kq + 4]);
                af[mt][3] = __float_as_uint(as[(r + 8) * SSTR + kq + 4]);
            }
            #pragma unroll
            for (int nt = 0; nt < 4; nt++) {
                int c = wn * 32 + nt * 8 + g;
                bf[nt][0] = __float_as_uint(bs[c * SSTR + kq]);
                bf[nt][1] = __float_as_uint(bs[c * SSTR + kq + 4]);
            }
            #pragma unroll
            for (int mt = 0; mt < 2; mt++)
                #pragma unroll
                for (int nt = 0; nt < 4; nt++)
                    mma_tf32(acc[mt][nt], af[mt], bf[nt]);
        }
        __syncthreads();
        if (kt + 2 < nTiles) prefetch(s, kt + 2);
    }

    #pragma unroll
    for (int mt = 0; mt < 2; mt++) {
        #pragma unroll
        for (int h = 0; h < 2; h++) {
            int m = mBase + wm * 32 + mt * 16 + g + h * 8;
            size_t dstrow;
            if (EPI == 1) dstrow = (size_t)win_to_spatial(m) * Nd;
            else          dstrow = (size_t)m * Nd;
            #pragma unroll
            for (int nt = 0; nt < 4; nt++) {
                #pragma unroll
                for (int e = 0; e < 2; e++) {
                    int n = nBase + wn * 32 + nt * 8 + 2 * l4 + e;
                    if (n < Nd) {
                        float v = acc[mt][nt][h * 2 + e] + bias[n];
                        if (EPI == 0) {
                            Cout[dstrow + n] = v;
                        } else if (EPI == 1) {
                            Cout[dstrow + n] = res[dstrow + n] + v;
                        } else if (EPI == 2) {
                            float gl = 0.5f * v * (1.0f + erff(v * 0.70710678118654752f));
                            Cout[dstrow + n] = round_tf32(gl);
                        } else {
                            Cout[dstrow + n] = res[dstrow + n] + v;
                        }
                    }
                }
            }
        }
    }
}

// ---------------- tensor-core windowed attention (ILP-restructured) ----------
// Block per (window, head), 256 threads = 8 warps.
// S-phase: warp w (<7) owns m-tile w; 13 independent n-tile accumulators,
// A-fragment loaded once per k8-step. PV-phase: warp w owns m-tile w, 4
// independent n-accumulators over 13 k8-steps.
// smem floats: q[112*36] | k[104*36] | vt[32*108] | S[112*108]
#define AQ_OFF 0
#define AK_OFF 4032
#define AV_OFF 7776
#define AS_OFF 11232
#define ASTR_QK 36
#define ASTR_S  108
#define ATTN_SMEM ((11232 + 112 * 108) * 4)   // 93312 B

__global__ void __launch_bounds__(256)
attn_kernel(const float* __restrict__ qkv, const float* __restrict__ mask,
            float* __restrict__ out) {
    int blk  = blockIdx.x;
    int win  = blk / HEADS;
    int head = blk - win * HEADS;
    int wi   = win & 1023;
    extern __shared__ float sm[];
    float* q  = sm + AQ_OFF;
    float* k  = sm + AK_OFF;
    float* vt = sm + AV_OFF;
    float* S  = sm + AS_OFF;
    int tid = threadIdx.x;
    int lane = tid & 31, warp = tid >> 5;
    int g = lane >> 2, l4 = lane & 3;
    const float scale = 0.17677669529663687f;

    const float* base = qkv + (size_t)(win * NN) * (3 * CC) + head * HD;

    // stage q (112 rows, zero pad), k (104 rows, zero pad) — coalesced reads
    for (int e = tid; e < 112 * 32; e += 256) {
        int i = e >> 5, d = e & 31;
        q[i * ASTR_QK + d] = (i < NN) ? round_tf32(base[(size_t)i * (3 * CC) + d] * scale) : 0.0f;
    }
    for (int e = tid; e < 104 * 32; e += 256) {
        int i = e >> 5, d = e & 31;
        k[i * ASTR_QK + d] = (i < NN) ? round_tf32(base[(size_t)i * (3 * CC) + CC + d]) : 0.0f;
    }
    // zero vt pad columns (j >= 98) once
    for (int e = tid; e < 32 * (ASTR_S - NN); e += 256) {
        int d = e / (ASTR_S - NN), j = NN + e % (ASTR_S - NN);
        vt[d * ASTR_S + j] = 0.0f;
    }
    // stage v: COALESCED gmem read (row-contiguous), transposed smem write
    for (int e = tid; e < NN * 32; e += 256) {
        int i = e >> 5, d = e & 31;
        vt[d * ASTR_S + i] = round_tf32(base[(size_t)i * (3 * CC) + 2 * CC + d]);
    }
    __syncthreads();

    // ---- S = q k^T : warp w -> m-tile w; 13 independent n-accumulators ----
    if (warp < 7) {
        int mt = warp;
        float acc[13][4];
        #pragma unroll
        for (int nt = 0; nt < 13; nt++)
            #pragma unroll
            for (int e = 0; e < 4; e++) acc[nt][e] = 0.0f;

        int r = mt * 16 + g;
        #pragma unroll
        for (int kk = 0; kk < 32; kk += 8) {
            int kq = kk + l4;
            uint32_t af[4];
            af[0] = __float_as_uint(q[r * ASTR_QK + kq]);
            af[1] = __float_as_uint(q[(r + 8) * ASTR_QK + kq]);
            af[2] = __float_as_uint(q[r * ASTR_QK + kq + 4]);
            af[3] = __float_as_uint(q[(r + 8) * ASTR_QK + kq + 4]);
            #pragma unroll
            for (int nt = 0; nt < 13; nt++) {
                uint32_t bf[2];
                int c = nt * 8 + g;
                bf[0] = __float_as_uint(k[c * ASTR_QK + kq]);
                bf[1] = __float_as_uint(k[c * ASTR_QK + kq + 4]);
                mma_tf32(acc[nt], af, bf);
            }
        }
        #pragma unroll
        for (int nt = 0; nt < 13; nt++) {
            int c0 = nt * 8 + 2 * l4;
            S[r * ASTR_S + c0]           = acc[nt][0];
            S[r * ASTR_S + c0 + 1]       = acc[nt][1];
            S[(r + 8) * ASTR_S + c0]     = acc[nt][2];
            S[(r + 8) * ASTR_S + c0 + 1] = acc[nt][3];
        }
    }
    __syncthreads();

    // ---- softmax rows (warp per row), mask inline; P tf32-rounded ----
    const float* mk = mask + (size_t)wi * (NN * NN);
    for (int i = warp; i < NN; i += 8) {
        float mx = -1e30f;
        for (int j = lane; j < NN; j += 32) {
            float v = S[i * ASTR_S + j] + mk[i * NN + j];
            S[i * ASTR_S + j] = v;
            mx = fmaxf(mx, v);
        }
        #pragma unroll
        for (int o = 16; o; o >>= 1) mx = fmaxf(mx, __shfl_xor_sync(0xffffffffu, mx, o));
        float sum = 0.0f;
        for (int j = lane; j < NN; j += 32) {
            float ev = __expf(S[i * ASTR_S + j] - mx);
            S[i * ASTR_S + j] = ev;
            sum += ev;
        }
        #pragma unroll
        for (int o = 16; o; o >>= 1) sum += __shfl_xor_sync(0xffffffffu, sum, o);
        float inv = 1.0f / sum;
        for (int j = lane; j < NN; j += 32)
            S[i * ASTR_S + j] = round_tf32(S[i * ASTR_S + j] * inv);
    }
    __syncthreads();

    // ---- O = P @ V : warp w -> m-tile w; 4 independent n-accumulators ----
    if (warp < 7) {
        int mt = warp;
        float acc[4][4];
        #pragma unroll
        for (int nt = 0; nt < 4; nt++)
            #pragma unroll
            for (int e = 0; e < 4; e++) acc[nt][e] = 0.0f;

        int r = mt * 16 + g;
        #pragma unroll
        for (int kt = 0; kt < 13; kt++) {
            int kq = kt * 8 + l4;
            uint32_t af[4];
            af[0] = __float_as_uint(S[r * ASTR_S + kq]);
            af[1] = __float_as_uint(S[(r + 8) * ASTR_S + kq]);
            af[2] = __float_as_uint(S[r * ASTR_S + kq + 4]);
            af[3] = __float_as_uint(S[(r + 8) * ASTR_S + kq + 4]);
            #pragma unroll
            for (int nt = 0; nt < 4; nt++) {
                uint32_t bf[2];
                int c = nt * 8 + g;
                bf[0] = __float_as_uint(vt[c * ASTR_S + kq]);
                bf[1] = __float_as_uint(vt[c * ASTR_S + kq + 4]);
                mma_tf32(acc[nt], af, bf);
            }
        }
        size_t ob = (size_t)(win * NN) * CC + head * HD;
        #pragma unroll
        for (int nt = 0; nt < 4; nt++) {
            int c0 = nt * 8 + 2 * l4;
            if (r < NN) {
                out[ob + (size_t)r * CC + c0]     = round_tf32(acc[nt][0]);
                out[ob + (size_t)r * CC + c0 + 1] = round_tf32(acc[nt][1]);
            }
            if (r + 8 < NN) {
                out[ob + (size_t)(r + 8) * CC + c0]     = round_tf32(acc[nt][2]);
                out[ob + (size_t)(r + 8) * CC + c0 + 1] = round_tf32(acc[nt][3]);
            }
        }
    }
}

// ---------------- launch ----------------
extern "C" void kernel_launch(void* const* d_in, const int* in_sizes, int n_in,
                              void* d_out, int out_size) {
    const float* x      = (const float*)d_in[0];
    const float* mask   = (const float*)d_in[1];
    const float* n1g    = (const float*)d_in[2];
    const float* n1b    = (const float*)d_in[3];
    const float* qkv_w  = (const float*)d_in[4];
    const float* qkv_b  = (const float*)d_in[5];
    const float* proj_w = (const float*)d_in[6];
    const float* proj_b = (const float*)d_in[7];
    const float* n2g    = (const float*)d_in[8];
    const float* n2b    = (const float*)d_in[9];
    const float* fc1_w  = (const float*)d_in[10];
    const float* fc1_b  = (const float*)d_in[11];
    const float* fc2_w  = (const float*)d_in[12];
    const float* fc2_b  = (const float*)d_in[13];
    float* out = (float*)d_out;

    float *xw, *qkvb, *ao, *x1, *h2, *hid, *wr;
    cudaGetSymbolAddress((void**)&xw,   g_xw);
    cudaGetSymbolAddress((void**)&qkvb, g_qkv);
    cudaGetSymbolAddress((void**)&ao,   g_ao);
    cudaGetSymbolAddress((void**)&x1,   g_x1);
    cudaGetSymbolAddress((void**)&h2,   g_h2);
    cudaGetSymbolAddress((void**)&hid,  g_hid);
    cudaGetSymbolAddress((void**)&wr,   g_wr);

    cudaFuncSetAttribute(attn_kernel, cudaFuncAttributeMaxDynamicSharedMemorySize,
                         ATTN_SMEM);

    const int mtiles = TT / GBM;   // 1568

    // 0) round weights to tf32 (tiny)
    round_weights_kernel<<<(WTOT + 255) / 256, 256>>>(qkv_w, proj_w, fc1_w, fc2_w, wr);
    // 1) LN1 + shift + window partition (tf32-rounded out)
    ln_kernel<<<TT / 4, 128>>>(x, n1g, n1b, xw, 1);
    // 2) qkv = xw @ qkv_w^T + qkv_b   (N=288)
    gemm_kernel<0><<<dim3(5, mtiles), 256>>>(xw, wr + WQKV_OFF, qkv_b, qkvb, nullptr,
                                             TT, 3 * CC, CC);
    // 3) windowed attention (tensor-core, ILP)
    attn_kernel<<<BW * HEADS, 256, ATTN_SMEM>>>(qkvb, mask, ao);
    // 4) proj + window reverse + unshift + residual(x) -> x1
    gemm_kernel<1><<<dim3(2, mtiles), 256>>>(ao, wr + WPROJ_OFF, proj_b, x1, x,
                                             TT, CC, CC);
    // 5) LN2 (tf32-rounded out)
    ln_kernel<<<TT / 4, 128>>>(x1, n2g, n2b, h2, 0);
    // 6) fc1 + exact GELU (tf32-rounded out)
    gemm_kernel<2><<<dim3(6, mtiles), 256>>>(h2, wr + WFC1_OFF, fc1_b, hid, nullptr,
                                             TT, HID, CC);
    // 7) fc2 + residual(x1) -> out
    gemm_kernel<3><<<dim3(2, mtiles), 256>>>(hid, wr + WFC2_OFF, fc2_b, out, x1,
                                             TT, CC, HID);
}

// round 11
// speedup vs baseline: 1.6759x; 1.6759x over previous
#include <cuda_runtime.h>
#include <cstdint>
#include <cstdio>

// ---------------- problem constants ----------------
#define BB   2
#define DD   32
#define HH   56
#define WW   56
#define CC   96
#define HEADS 3
#define HD   32
#define NN   98          // window tokens = 2*7*7
#define NWIN 1024        // windows per batch = 16*8*8
#define BW   (BB*NWIN)   // 2048 windows
#define TT   (BW*NN)     // 200704 tokens
#define HID  384

// ---------------- scratch (device globals; allocation-free) ----------------
__device__ float g_xw  [(size_t)TT*CC];     // LN1 out (tf32-rounded)
__device__ float g_qkv [(size_t)TT*3*CC];
__device__ float g_ao  [(size_t)TT*CC];     // attn out (tf32-rounded)
__device__ float g_x1  [(size_t)TT*CC];
__device__ float g_h2  [(size_t)TT*CC];     // LN2 out (tf32-rounded)
__device__ float g_hid [(size_t)TT*HID];    // gelu out (tf32-rounded)

// rounded weights: qkv | proj | fc1 | fc2
#define WQKV_OFF 0
#define WPROJ_OFF 27648
#define WFC1_OFF 36864
#define WFC2_OFF 73728
#define WTOT     110592
__device__ float g_wr[WTOT];

__device__ __forceinline__ uint32_t cvt_tf32(float x) {
    uint32_t r;
    asm("cvt.rna.tf32.f32 %0, %1;" : "=r"(r) : "f"(x));
    return r;
}
__device__ __forceinline__ float round_tf32(float x) {
    return __uint_as_float(cvt_tf32(x));
}

// Map window-token index -> spatial token index (shifted gather/scatter).
__device__ __forceinline__ int win_to_spatial(int t) {
    int win = t / NN, n = t - win * NN;
    int b  = win >> 10;
    int wi = win & 1023;
    int d0 = wi >> 6, h0 = (wi >> 3) & 7, w0 = wi & 7;
    int dd = n / 49;  int r = n - dd * 49;
    int hh = r / 7;   int ww = r - hh * 7;
    int d = d0 * 2 + dd + 1; if (d >= DD) d -= DD;
    int h = h0 * 7 + hh + 3; if (h >= HH) h -= HH;
    int w = w0 * 7 + ww + 3; if (w >= WW) w -= WW;
    return ((b * DD + d) * HH + h) * WW + w;
}

// ---------------- weight rounding (one-shot, tiny) ----------------
__global__ void round_weights_kernel(const float* __restrict__ qkv_w,
                                     const float* __restrict__ proj_w,
                                     const float* __restrict__ fc1_w,
                                     const float* __restrict__ fc2_w,
                                     float* __restrict__ wr) {
    int i = blockIdx.x * 256 + threadIdx.x;
    if (i < WTOT) {
        float v;
        if      (i < WPROJ_OFF) v = qkv_w[i - WQKV_OFF];
        else if (i < WFC1_OFF)  v = proj_w[i - WPROJ_OFF];
        else if (i < WFC2_OFF)  v = fc1_w[i - WFC1_OFF];
        else                    v = fc2_w[i - WFC2_OFF];
        wr[i] = round_tf32(v);
    }
}

// ---------------- LayerNorm (warp per token, C=96=3*32), tf32-rounded out ----
__global__ void ln_kernel(const float* __restrict__ in,
                          const float* __restrict__ g,
                          const float* __restrict__ bta,
                          float* __restrict__ out, int gather) {
    int t = blockIdx.x * 4 + (threadIdx.x >> 5);
    int lane = threadIdx.x & 31;
    size_t src = gather ? (size_t)win_to_spatial(t) * CC : (size_t)t * CC;
    float x0 = in[src + lane];
    float x1 = in[src + lane + 32];
    float x2 = in[src + lane + 64];
    float s  = x0 + x1 + x2;
    float sq = x0 * x0 + x1 * x1 + x2 * x2;
    #pragma unroll
    for (int o = 16; o; o >>= 1) {
        s  += __shfl_xor_sync(0xffffffffu, s,  o);
        sq += __shfl_xor_sync(0xffffffffu, sq, o);
    }
    float mean = s * (1.0f / 96.0f);
    float var  = sq * (1.0f / 96.0f) - mean * mean;
    float rst  = rsqrtf(var + 1e-5f);
    size_t dst = (size_t)t * CC;
    out[dst + lane]      = round_tf32((x0 - mean) * rst * g[lane]      + bta[lane]);
    out[dst + lane + 32] = round_tf32((x1 - mean) * rst * g[lane + 32] + bta[lane + 32]);
    out[dst + lane + 64] = round_tf32((x2 - mean) * rst * g[lane + 64] + bta[lane + 64]);
}

// ---------------- shared mma helper (GEMMs only) ----------------
__device__ __forceinline__ void mma_tf32(float* d, const uint32_t* a, const uint32_t* b) {
    asm volatile(
        "mma.sync.aligned.m16n8k8.row.col.f32.tf32.tf32.f32 "
        "{%0,%1,%2,%3}, {%4,%5,%6,%7}, {%8,%9}, {%0,%1,%2,%3};\n"
        : "+f"(d[0]), "+f"(d[1]), "+f"(d[2]), "+f"(d[3])
        : "r"(a[0]), "r"(a[1]), "r"(a[2]), "r"(a[3]),
          "r"(b[0]), "r"(b[1]));
}

// ---------------- tf32 tensor-core GEMM: C[M,Nd] = A[M,K] * W[Nd,K]^T + bias ----
#define GBM 128
#define GBN 64
#define GBK 32
#define SSTR 36

__device__ __forceinline__ void cp16(uint32_t dst_smem, const float* src, bool pred) {
    int sz = pred ? 16 : 0;
    asm volatile("cp.async.ca.shared.global [%0], [%1], 16, %2;\n"
                 :: "r"(dst_smem), "l"(src), "r"(sz));
}

template<int EPI>
__global__ void __launch_bounds__(256)
gemm_kernel(const float* __restrict__ A, const float* __restrict__ Wt,
            const float* __restrict__ bias, float* __restrict__ Cout,
            const float* __restrict__ res, int M, int Nd, int K) {
    __shared__ float As[2][GBM * SSTR];
    __shared__ float Bs[2][GBN * SSTR];

    int tid  = threadIdx.x;
    int lane = tid & 31, warp = tid >> 5;
    int wm = warp >> 1;
    int wn = warp & 1;
    int g  = lane >> 2, l4 = lane & 3;
    int mBase = blockIdx.y * GBM;
    int nBase = blockIdx.x * GBN;

    int lr = tid >> 3;
    int lc = (tid & 7) * 4;

    const float* Ap = A + (size_t)(mBase + lr) * K + lc;
    const float* Bp = Wt + (size_t)(nBase + lr) * K + lc;

    uint32_t asb = (uint32_t)__cvta_generic_to_shared(&As[0][0]);
    uint32_t bsb = (uint32_t)__cvta_generic_to_shared(&Bs[0][0]);

    float acc[2][4][4];
    #pragma unroll
    for (int mt = 0; mt < 2; mt++)
        #pragma unroll
        for (int nt = 0; nt < 4; nt++)
            #pragma unroll
            for (int e = 0; e < 4; e++) acc[mt][nt][e] = 0.0f;

    int nTiles = K / GBK;

    auto prefetch = [&](int s, int kt) {
        uint32_t ad = asb + (uint32_t)(s * GBM * SSTR + lr * SSTR + lc) * 4;
        uint32_t bd = bsb + (uint32_t)(s * GBN * SSTR + lr * SSTR + lc) * 4;
        int kb = kt * GBK;
        #pragma unroll
        for (int i = 0; i < 4; i++)
            cp16(ad + i * 32 * SSTR * 4, Ap + (size_t)i * 32 * K + kb, true);
        #pragma unroll
        for (int i = 0; i < 2; i++)
            cp16(bd + i * 32 * SSTR * 4, Bp + (size_t)i * 32 * K + kb,
                 (nBase + lr + i * 32) < Nd);
        asm volatile("cp.async.commit_group;\n" ::);
    };

    prefetch(0, 0);
    prefetch(1, 1);

    for (int kt = 0; kt < nTiles; kt++) {
        if (kt + 1 < nTiles)
            asm volatile("cp.async.wait_group 1;\n" ::);
        else
            asm volatile("cp.async.wait_group 0;\n" ::);
        __syncthreads();

        int s = kt & 1;
        const float* as = As[s];
        const float* bs = Bs[s];

        #pragma unroll
        for (int kk = 0; kk < GBK; kk += 8) {
            int kq = kk + l4;
            uint32_t af[2][4], bf[4][2];
            #pragma unroll
            for (int mt = 0; mt < 2; mt++) {
                int r = wm * 32 + mt * 16 + g;
                af[mt][0] = __float_as_uint(as[r * SSTR + kq]);
                af[mt][1] = __float_as_uint(as[(r + 8) * SSTR + kq]);
                af[mt][2] = __float_as_uint(as[r * SSTR + kq + 4]);
                af[mt][3] = __float_as_uint(as[(r + 8) * SSTR + kq + 4]);
            }
            #pragma unroll
            for (int nt = 0; nt < 4; nt++) {
                int c = wn * 32 + nt * 8 + g;
                bf[nt][0] = __float_as_uint(bs[c * SSTR + kq]);
                bf[nt][1] = __float_as_uint(bs[c * SSTR + kq + 4]);
            }
            #pragma unroll
            for (int mt = 0; mt < 2; mt++)
                #pragma unroll
                for (int nt = 0; nt < 4; nt++)
                    mma_tf32(acc[mt][nt], af[mt], bf[nt]);
        }
        __syncthreads();
        if (kt + 2 < nTiles) prefetch(s, kt + 2);
    }

    #pragma unroll
    for (int mt = 0; mt < 2; mt++) {
        #pragma unroll
        for (int h = 0; h < 2; h++) {
            int m = mBase + wm * 32 + mt * 16 + g + h * 8;
            size_t dstrow;
            if (EPI == 1) dstrow = (size_t)win_to_spatial(m) * Nd;
            else          dstrow = (size_t)m * Nd;
            #pragma unroll
            for (int nt = 0; nt < 4; nt++) {
                #pragma unroll
                for (int e = 0; e < 2; e++) {
                    int n = nBase + wn * 32 + nt * 8 + 2 * l4 + e;
                    if (n < Nd) {
                        float v = acc[mt][nt][h * 2 + e] + bias[n];
                        if (EPI == 0) {
                            Cout[dstrow + n] = v;
                        } else if (EPI == 1) {
                            Cout[dstrow + n] = res[dstrow + n] + v;
                        } else if (EPI == 2) {
                            float gl = 0.5f * v * (1.0f + erff(v * 0.70710678118654752f));
                            Cout[dstrow + n] = round_tf32(gl);
                        } else {
                            Cout[dstrow + n] = res[dstrow + n] + v;
                        }
                    }
                }
            }
        }
    }
}

// ---------------- scalar windowed attention, float4 4x4 tiles + analytic mask --
// Block per (window, head), 256 threads.
// smem floats: qt[32][104] (q^T) | kt[32][104] (k^T) | v[100][36] | S[100][104]
//              + labs[104] ints
// S-phase: 25x25 4x4 tiles, per d-step 2x LDS.128 for 16 FMA.
// PV-phase: 25x8 4x4 tiles, per 4-j chunk 8x LDS.128 for 64 FMA.
#define AQT_OFF 0
#define AKT_OFF 3328
#define AV_OFF  6656
#define AS_OFF  10256
#define ALAB_OFF 20656
#define VSTR 36
#define PSTR 104
#define ATTN_SMEM (20656 * 4 + 104 * 4)   // 83040 B

__device__ __forceinline__ int region3(int c, int lo, int hi) {
    // 0 if c < lo, 1 if lo <= c < hi, 2 if c >= hi
    return (c >= lo) + (c >= hi);
}

__global__ void __launch_bounds__(256)
attn_kernel(const float* __restrict__ qkv, float* __restrict__ out) {
    int blk  = blockIdx.x;
    int win  = blk / HEADS;
    int head = blk - win * HEADS;
    int wi   = win & 1023;
    extern __shared__ float sm[];
    float* qt = sm + AQT_OFF;
    float* kt = sm + AKT_OFF;
    float* v  = sm + AV_OFF;
    float* S  = sm + AS_OFF;
    int* labs = (int*)(sm + ALAB_OFF);
    int tid = threadIdx.x;
    const float scale = 0.17677669529663687f;

    const float* base = qkv + (size_t)(win * NN) * (3 * CC) + head * HD;

    // region labels from window coords (mask is analytic; no gmem mask)
    if (tid < NN) {
        int d0 = wi >> 6, h0 = (wi >> 3) & 7, w0 = wi & 7;
        int dd = tid / 49; int r = tid - dd * 49;
        int hh = r / 7;    int ww = r - hh * 7;
        int d = d0 * 2 + dd;       // unshifted coords (mask built pre-roll)
        int h = h0 * 7 + hh;
        int w = w0 * 7 + ww;
        labs[tid] = region3(d, DD - 2, DD - 1) * 9
                  + region3(h, HH - 7, HH - 3) * 3
                  + region3(w, WW - 7, WW - 3);
    }

    // stage q^T, k^T (coalesced gmem reads, transposed smem writes), zero pads
    for (int e = tid; e < 104 * 32; e += 256) {
        int i = e >> 5, d = e & 31;
        qt[d * PSTR + i] = (i < NN) ? base[(size_t)i * (3 * CC) + d] * scale : 0.0f;
        kt[d * PSTR + i] = (i < NN) ? base[(size_t)i * (3 * CC) + CC + d] : 0.0f;
    }
    // stage v row-major [j][d], zero pad rows 98-99
    for (int e = tid; e < 100 * 32; e += 256) {
        int i = e >> 5, d = e & 31;
        v[i * VSTR + d] = (i < NN) ? base[(size_t)i * (3 * CC) + 2 * CC + d] : 0.0f;
    }
    __syncthreads();

    // ---- S = q k^T : 25x25 grid of 4x4 tiles ----
    for (int u = tid; u < 625; u += 256) {
        int it = u / 25, jt = u - it * 25;
        int i0 = it * 4, j0 = jt * 4;
        float s[4][4];
        #pragma unroll
        for (int a = 0; a < 4; a++)
            #pragma unroll
            for (int b = 0; b < 4; b++) s[a][b] = 0.0f;
        #pragma unroll 8
        for (int d = 0; d < 32; d++) {
            float4 qa = *(const float4*)&qt[d * PSTR + i0];
            float4 kb = *(const float4*)&kt[d * PSTR + j0];
            float qv[4] = {qa.x, qa.y, qa.z, qa.w};
            float kv[4] = {kb.x, kb.y, kb.z, kb.w};
            #pragma unroll
            for (int a = 0; a < 4; a++)
                #pragma unroll
                for (int b = 0; b < 4; b++)
                    s[a][b] = fmaf(qv[a], kv[b], s[a][b]);
        }
        #pragma unroll
        for (int a = 0; a < 4; a++)
            *(float4*)&S[(i0 + a) * PSTR + j0] =
                make_float4(s[a][0], s[a][1], s[a][2], s[a][3]);
    }
    __syncthreads();

    // ---- softmax rows (warp per row), analytic mask inline ----
    int warp = tid >> 5, lane = tid & 31;
    for (int i = warp; i < NN; i += 8) {
        int li = labs[i];
        float mx = -1e30f;
        for (int j = lane; j < NN; j += 32) {
            float val = S[i * PSTR + j] + ((labs[j] == li) ? 0.0f : -100.0f);
            S[i * PSTR + j] = val;
            mx = fmaxf(mx, val);
        }
        #pragma unroll
        for (int o = 16; o; o >>= 1) mx = fmaxf(mx, __shfl_xor_sync(0xffffffffu, mx, o));
        float sum = 0.0f;
        for (int j = lane; j < NN; j += 32) {
            float ev = __expf(S[i * PSTR + j] - mx);
            S[i * PSTR + j] = ev;
            sum += ev;
        }
        #pragma unroll
        for (int o = 16; o; o >>= 1) sum += __shfl_xor_sync(0xffffffffu, sum, o);
        float inv = 1.0f / sum;
        for (int j = lane; j < NN; j += 32) S[i * PSTR + j] *= inv;
        // cols 98-103 remain 0 (kt pads were zero, never exp'd) -> PV-safe
    }
    __syncthreads();

    // ---- O = P @ V : 25x8 grid of 4x4 tiles; K=100 in chunks of 4 ----
    for (int u = tid; u < 200; u += 256) {
        int it = u >> 3, dt = u & 7;
        int i0 = it * 4, d0 = dt * 4;
        float o[4][4];
        #pragma unroll
        for (int a = 0; a < 4; a++)
            #pragma unroll
            for (int b = 0; b < 4; b++) o[a][b] = 0.0f;
        #pragma unroll 5
        for (int jc = 0; jc < 25; jc++) {
            int j0 = jc * 4;
            float4 p[4], vv[4];
            #pragma unroll
            for (int a = 0; a < 4; a++)
                p[a] = *(const float4*)&S[(i0 + a) * PSTR + j0];
            #pragma unroll
            for (int b = 0; b < 4; b++)
                vv[b] = *(const float4*)&v[(j0 + b) * VSTR + d0];
            #pragma unroll
            for (int a = 0; a < 4; a++) {
                o[a][0] = fmaf(p[a].x, vv[0].x, o[a][0]);
                o[a][1] = fmaf(p[a].x, vv[0].y, o[a][1]);
                o[a][2] = fmaf(p[a].x, vv[0].z, o[a][2]);
                o[a][3] = fmaf(p[a].x, vv[0].w, o[a][3]);
                o[a][0] = fmaf(p[a].y, vv[1].x, o[a][0]);
                o[a][1] = fmaf(p[a].y, vv[1].y, o[a][1]);
                o[a][2] = fmaf(p[a].y, vv[1].z, o[a][2]);
                o[a][3] = fmaf(p[a].y, vv[1].w, o[a][3]);
                o[a][0] = fmaf(p[a].z, vv[2].x, o[a][0]);
                o[a][1] = fmaf(p[a].z, vv[2].y, o[a][1]);
                o[a][2] = fmaf(p[a].z, vv[2].z, o[a][2]);
                o[a][3] = fmaf(p[a].z, vv[2].w, o[a][3]);
                o[a][0] = fmaf(p[a].w, vv[3].x, o[a][0]);
                o[a][1] = fmaf(p[a].w, vv[3].y, o[a][1]);
                o[a][2] = fmaf(p[a].w, vv[3].z, o[a][2]);
                o[a][3] = fmaf(p[a].w, vv[3].w, o[a][3]);
            }
        }
        size_t ob = (size_t)(win * NN) * CC + head * HD + d0;
        #pragma unroll
        for (int a = 0; a < 4; a++) {
            int i = i0 + a;
            if (i < NN) {
                *(float4*)&out[ob + (size_t)i * CC] =
                    make_float4(round_tf32(o[a][0]), round_tf32(o[a][1]),
                                round_tf32(o[a][2]), round_tf32(o[a][3]));
            }
        }
    }
}

// ---------------- launch ----------------
extern "C" void kernel_launch(void* const* d_in, const int* in_sizes, int n_in,
                              void* d_out, int out_size) {
    const float* x      = (const float*)d_in[0];
    // d_in[1] = mask_matrix (unused: mask computed analytically)
    const float* n1g    = (const float*)d_in[2];
    const float* n1b    = (const float*)d_in[3];
    const float* qkv_w  = (const float*)d_in[4];
    const float* qkv_b  = (const float*)d_in[5];
    const float* proj_w = (const float*)d_in[6];
    const float* proj_b = (const float*)d_in[7];
    const float* n2g    = (const float*)d_in[8];
    const float* n2b    = (const float*)d_in[9];
    const float* fc1_w  = (const float*)d_in[10];
    const float* fc1_b  = (const float*)d_in[11];
    const float* fc2_w  = (const float*)d_in[12];
    const float* fc2_b  = (const float*)d_in[13];
    float* out = (float*)d_out;

    float *xw, *qkvb, *ao, *x1, *h2, *hid, *wr;
    cudaGetSymbolAddress((void**)&xw,   g_xw);
    cudaGetSymbolAddress((void**)&qkvb, g_qkv);
    cudaGetSymbolAddress((void**)&ao,   g_ao);
    cudaGetSymbolAddress((void**)&x1,   g_x1);
    cudaGetSymbolAddress((void**)&h2,   g_h2);
    cudaGetSymbolAddress((void**)&hid,  g_hid);
    cudaGetSymbolAddress((void**)&wr,   g_wr);

    cudaFuncSetAttribute(attn_kernel, cudaFuncAttributeMaxDynamicSharedMemorySize,
                         ATTN_SMEM);

    const int mtiles = TT / GBM;   // 1568

    // 0) round weights to tf32 (tiny)
    round_weights_kernel<<<(WTOT + 255) / 256, 256>>>(qkv_w, proj_w, fc1_w, fc2_w, wr);
    // 1) LN1 + shift + window partition (tf32-rounded out)
    ln_kernel<<<TT / 4, 128>>>(x, n1g, n1b, xw, 1);
    // 2) qkv = xw @ qkv_w^T + qkv_b   (N=288)
    gemm_kernel<0><<<dim3(5, mtiles), 256>>>(xw, wr + WQKV_OFF, qkv_b, qkvb, nullptr,
                                             TT, 3 * CC, CC);
    // 3) windowed attention (scalar 4x4 float4, analytic mask)
    attn_kernel<<<BW * HEADS, 256, ATTN_SMEM>>>(qkvb, ao);
    // 4) proj + window reverse + unshift + residual(x) -> x1
    gemm_kernel<1><<<dim3(2, mtiles), 256>>>(ao, wr + WPROJ_OFF, proj_b, x1, x,
                                             TT, CC, CC);
    // 5) LN2 (tf32-rounded out)
    ln_kernel<<<TT / 4, 128>>>(x1, n2g, n2b, h2, 0);
    // 6) fc1 + exact GELU (tf32-rounded out)
    gemm_kernel<2><<<dim3(6, mtiles), 256>>>(h2, wr + WFC1_OFF, fc1_b, hid, nullptr,
                                             TT, HID, CC);
    // 7) fc2 + residual(x1) -> out
    gemm_kernel<3><<<dim3(2, mtiles), 256>>>(hid, wr + WFC2_OFF, fc2_b, out, x1,
                                             TT, CC, HID);
}

// round 12
// speedup vs baseline: 1.9172x; 1.1439x over previous
#include <cuda_runtime.h>
#include <cstdint>
#include <cstdio>

// ---------------- problem constants ----------------
#define BB   2
#define DD   32
#define HH   56
#define WW   56
#define CC   96
#define HEADS 3
#define HD   32
#define NN   98          // window tokens = 2*7*7
#define NWIN 1024        // windows per batch = 16*8*8
#define BW   (BB*NWIN)   // 2048 windows
#define TT   (BW*NN)     // 200704 tokens
#define HID  384

// ---------------- scratch (device globals; allocation-free) ----------------
__device__ float g_xw  [(size_t)TT*CC];     // LN1 out (tf32-rounded)
__device__ float g_qkv [(size_t)TT*3*CC];
__device__ float g_ao  [(size_t)TT*CC];     // attn out (tf32-rounded)
__device__ float g_x1  [(size_t)TT*CC];
__device__ float g_h2  [(size_t)TT*CC];     // LN2 out (tf32-rounded)
__device__ float g_hid [(size_t)TT*HID];    // gelu out (tf32-rounded)

// rounded weights: qkv | proj | fc1 | fc2
#define WQKV_OFF 0
#define WPROJ_OFF 27648
#define WFC1_OFF 36864
#define WFC2_OFF 73728
#define WTOT     110592
__device__ float g_wr[WTOT];

__device__ __forceinline__ uint32_t cvt_tf32(float x) {
    uint32_t r;
    asm("cvt.rna.tf32.f32 %0, %1;" : "=r"(r) : "f"(x));
    return r;
}
__device__ __forceinline__ float round_tf32(float x) {
    return __uint_as_float(cvt_tf32(x));
}

// Map window-token index -> spatial token index (shifted gather/scatter).
__device__ __forceinline__ int win_to_spatial(int t) {
    int win = t / NN, n = t - win * NN;
    int b  = win >> 10;
    int wi = win & 1023;
    int d0 = wi >> 6, h0 = (wi >> 3) & 7, w0 = wi & 7;
    int dd = n / 49;  int r = n - dd * 49;
    int hh = r / 7;   int ww = r - hh * 7;
    int d = d0 * 2 + dd + 1; if (d >= DD) d -= DD;
    int h = h0 * 7 + hh + 3; if (h >= HH) h -= HH;
    int w = w0 * 7 + ww + 3; if (w >= WW) w -= WW;
    return ((b * DD + d) * HH + h) * WW + w;
}

// ---------------- weight rounding (one-shot, tiny) ----------------
__global__ void round_weights_kernel(const float* __restrict__ qkv_w,
                                     const float* __restrict__ proj_w,
                                     const float* __restrict__ fc1_w,
                                     const float* __restrict__ fc2_w,
                                     float* __restrict__ wr) {
    int i = blockIdx.x * 256 + threadIdx.x;
    if (i < WTOT) {
        float v;
        if      (i < WPROJ_OFF) v = qkv_w[i - WQKV_OFF];
        else if (i < WFC1_OFF)  v = proj_w[i - WPROJ_OFF];
        else if (i < WFC2_OFF)  v = fc1_w[i - WFC1_OFF];
        else                    v = fc2_w[i - WFC2_OFF];
        wr[i] = round_tf32(v);
    }
}

// ---------------- LayerNorm (warp per token, C=96=3*32), tf32-rounded out ----
__global__ void ln_kernel(const float* __restrict__ in,
                          const float* __restrict__ g,
                          const float* __restrict__ bta,
                          float* __restrict__ out, int gather) {
    int t = blockIdx.x * 4 + (threadIdx.x >> 5);
    int lane = threadIdx.x & 31;
    size_t src = gather ? (size_t)win_to_spatial(t) * CC : (size_t)t * CC;
    float x0 = in[src + lane];
    float x1 = in[src + lane + 32];
    float x2 = in[src + lane + 64];
    float s  = x0 + x1 + x2;
    float sq = x0 * x0 + x1 * x1 + x2 * x2;
    #pragma unroll
    for (int o = 16; o; o >>= 1) {
        s  += __shfl_xor_sync(0xffffffffu, s,  o);
        sq += __shfl_xor_sync(0xffffffffu, sq, o);
    }
    float mean = s * (1.0f / 96.0f);
    float var  = sq * (1.0f / 96.0f) - mean * mean;
    float rst  = rsqrtf(var + 1e-5f);
    size_t dst = (size_t)t * CC;
    out[dst + lane]      = round_tf32((x0 - mean) * rst * g[lane]      + bta[lane]);
    out[dst + lane + 32] = round_tf32((x1 - mean) * rst * g[lane + 32] + bta[lane + 32]);
    out[dst + lane + 64] = round_tf32((x2 - mean) * rst * g[lane + 64] + bta[lane + 64]);
}

// ---------------- shared mma helper (GEMMs only) ----------------
__device__ __forceinline__ void mma_tf32(float* d, const uint32_t* a, const uint32_t* b) {
    asm volatile(
        "mma.sync.aligned.m16n8k8.row.col.f32.tf32.tf32.f32 "
        "{%0,%1,%2,%3}, {%4,%5,%6,%7}, {%8,%9}, {%0,%1,%2,%3};\n"
        : "+f"(d[0]), "+f"(d[1]), "+f"(d[2]), "+f"(d[3])
        : "r"(a[0]), "r"(a[1]), "r"(a[2]), "r"(a[3]),
          "r"(b[0]), "r"(b[1]));
}

// ---------------- tf32 tensor-core GEMM: C[M,Nd] = A[M,K] * W[Nd,K]^T + bias ----
#define GBM 128
#define GBN 64
#define GBK 32
#define SSTR 36

__device__ __forceinline__ void cp16(uint32_t dst_smem, const float* src, bool pred) {
    int sz = pred ? 16 : 0;
    asm volatile("cp.async.ca.shared.global [%0], [%1], 16, %2;\n"
                 :: "r"(dst_smem), "l"(src), "r"(sz));
}

template<int EPI>
__global__ void __launch_bounds__(256)
gemm_kernel(const float* __restrict__ A, const float* __restrict__ Wt,
            const float* __restrict__ bias, float* __restrict__ Cout,
            const float* __restrict__ res, int M, int Nd, int K) {
    __shared__ float As[2][GBM * SSTR];
    __shared__ float Bs[2][GBN * SSTR];

    int tid  = threadIdx.x;
    int lane = tid & 31, warp = tid >> 5;
    int wm = warp >> 1;
    int wn = warp & 1;
    int g  = lane >> 2, l4 = lane & 3;
    int mBase = blockIdx.y * GBM;
    int nBase = blockIdx.x * GBN;

    int lr = tid >> 3;
    int lc = (tid & 7) * 4;

    const float* Ap = A + (size_t)(mBase + lr) * K + lc;
    const float* Bp = Wt + (size_t)(nBase + lr) * K + lc;

    uint32_t asb = (uint32_t)__cvta_generic_to_shared(&As[0][0]);
    uint32_t bsb = (uint32_t)__cvta_generic_to_shared(&Bs[0][0]);

    float acc[2][4][4];
    #pragma unroll
    for (int mt = 0; mt < 2; mt++)
        #pragma unroll
        for (int nt = 0; nt < 4; nt++)
            #pragma unroll
            for (int e = 0; e < 4; e++) acc[mt][nt][e] = 0.0f;

    int nTiles = K / GBK;

    auto prefetch = [&](int s, int kt) {
        uint32_t ad = asb + (uint32_t)(s * GBM * SSTR + lr * SSTR + lc) * 4;
        uint32_t bd = bsb + (uint32_t)(s * GBN * SSTR + lr * SSTR + lc) * 4;
        int kb = kt * GBK;
        #pragma unroll
        for (int i = 0; i < 4; i++)
            cp16(ad + i * 32 * SSTR * 4, Ap + (size_t)i * 32 * K + kb, true);
        #pragma unroll
        for (int i = 0; i < 2; i++)
            cp16(bd + i * 32 * SSTR * 4, Bp + (size_t)i * 32 * K + kb,
                 (nBase + lr + i * 32) < Nd);
        asm volatile("cp.async.commit_group;\n" ::);
    };

    prefetch(0, 0);
    prefetch(1, 1);

    for (int kt = 0; kt < nTiles; kt++) {
        if (kt + 1 < nTiles)
            asm volatile("cp.async.wait_group 1;\n" ::);
        else
            asm volatile("cp.async.wait_group 0;\n" ::);
        __syncthreads();

        int s = kt & 1;
        const float* as = As[s];
        const float* bs = Bs[s];

        #pragma unroll
        for (int kk = 0; kk < GBK; kk += 8) {
            int kq = kk + l4;
            uint32_t af[2][4], bf[4][2];
            #pragma unroll
            for (int mt = 0; mt < 2; mt++) {
                int r = wm * 32 + mt * 16 + g;
                af[mt][0] = __float_as_uint(as[r * SSTR + kq]);
                af[mt][1] = __float_as_uint(as[(r + 8) * SSTR + kq]);
                af[mt][2] = __float_as_uint(as[r * SSTR + kq + 4]);
                af[mt][3] = __float_as_uint(as[(r + 8) * SSTR + kq + 4]);
            }
            #pragma unroll
            for (int nt = 0; nt < 4; nt++) {
                int c = wn * 32 + nt * 8 + g;
                bf[nt][0] = __float_as_uint(bs[c * SSTR + kq]);
                bf[nt][1] = __float_as_uint(bs[c * SSTR + kq + 4]);
            }
            #pragma unroll
            for (int mt = 0; mt < 2; mt++)
                #pragma unroll
                for (int nt = 0; nt < 4; nt++)
                    mma_tf32(acc[mt][nt], af[mt], bf[nt]);
        }
        __syncthreads();
        if (kt + 2 < nTiles) prefetch(s, kt + 2);
    }

    #pragma unroll
    for (int mt = 0; mt < 2; mt++) {
        #pragma unroll
        for (int h = 0; h < 2; h++) {
            int m = mBase + wm * 32 + mt * 16 + g + h * 8;
            size_t dstrow;
            if (EPI == 1) dstrow = (size_t)win_to_spatial(m) * Nd;
            else          dstrow = (size_t)m * Nd;
            #pragma unroll
            for (int nt = 0; nt < 4; nt++) {
                #pragma unroll
                for (int e = 0; e < 2; e++) {
                    int n = nBase + wn * 32 + nt * 8 + 2 * l4 + e;
                    if (n < Nd) {
                        float v = acc[mt][nt][h * 2 + e] + bias[n];
                        if (EPI == 0) {
                            Cout[dstrow + n] = v;
                        } else if (EPI == 1) {
                            Cout[dstrow + n] = res[dstrow + n] + v;
                        } else if (EPI == 2) {
                            float gl = 0.5f * v * (1.0f + erff(v * 0.70710678118654752f));
                            Cout[dstrow + n] = round_tf32(gl);
                        } else {
                            Cout[dstrow + n] = res[dstrow + n] + v;
                        }
                    }
                }
            }
        }
    }
}

// ---------------- scalar windowed attention, float4 4x4 tiles + analytic mask --
// Block per (window, head), 256 threads, 66.5 KB smem -> 3 CTAs/SM.
// qt and v SHARE one union buffer: qt is dead after the S-phase; v is staged
// during the softmax phase (independent work, same barrier interval).
// smem floats: kt[32][104] | union{qt[32][104], v[100][36]} | S[100][100] | labs
#define AKT_OFF 0
#define AUN_OFF 3328                   // qt (3328 floats) / v (3600 floats)
#define AS_OFF  (AUN_OFF + 3600)       // 6928
#define ALAB_OFF (AS_OFF + 10000)      // 16928
#define VSTR 36
#define QSTR 104
#define SST  100
#define ATTN_SMEM ((16928 + 104) * 4)  // 68128 B

__device__ __forceinline__ int region3(int c, int lo, int hi) {
    return (c >= lo) + (c >= hi);
}

__global__ void __launch_bounds__(256)
attn_kernel(const float* __restrict__ qkv, float* __restrict__ out) {
    int blk  = blockIdx.x;
    int win  = blk / HEADS;
    int head = blk - win * HEADS;
    int wi   = win & 1023;
    extern __shared__ float sm[];
    float* kt = sm + AKT_OFF;
    float* qt = sm + AUN_OFF;      // union with v
    float* v  = sm + AUN_OFF;
    float* S  = sm + AS_OFF;
    int* labs = (int*)(sm + ALAB_OFF);
    int tid = threadIdx.x;
    const float scale = 0.17677669529663687f;

    const float* base = qkv + (size_t)(win * NN) * (3 * CC) + head * HD;

    // region labels from window coords (mask analytic; no gmem mask)
    if (tid < NN) {
        int d0 = wi >> 6, h0 = (wi >> 3) & 7, w0 = wi & 7;
        int dd = tid / 49; int r = tid - dd * 49;
        int hh = r / 7;    int ww = r - hh * 7;
        int d = d0 * 2 + dd;
        int h = h0 * 7 + hh;
        int w = w0 * 7 + ww;
        labs[tid] = region3(d, DD - 2, DD - 1) * 9
                  + region3(h, HH - 7, HH - 3) * 3
                  + region3(w, WW - 7, WW - 3);
    }

    // stage q^T, k^T (coalesced gmem reads, transposed smem writes), zero pads
    for (int e = tid; e < 104 * 32; e += 256) {
        int i = e >> 5, d = e & 31;
        qt[d * QSTR + i] = (i < NN) ? base[(size_t)i * (3 * CC) + d] * scale : 0.0f;
        kt[d * QSTR + i] = (i < NN) ? base[(size_t)i * (3 * CC) + CC + d] : 0.0f;
    }
    __syncthreads();

    // ---- S = q k^T : 25x25 grid of 4x4 tiles ----
    for (int u = tid; u < 625; u += 256) {
        int it = u / 25, jt = u - it * 25;
        int i0 = it * 4, j0 = jt * 4;
        float s[4][4];
        #pragma unroll
        for (int a = 0; a < 4; a++)
            #pragma unroll
            for (int b = 0; b < 4; b++) s[a][b] = 0.0f;
        #pragma unroll 8
        for (int d = 0; d < 32; d++) {
            float4 qa = *(const float4*)&qt[d * QSTR + i0];
            float4 kb = *(const float4*)&kt[d * QSTR + j0];
            float qv[4] = {qa.x, qa.y, qa.z, qa.w};
            float kv[4] = {kb.x, kb.y, kb.z, kb.w};
            #pragma unroll
            for (int a = 0; a < 4; a++)
                #pragma unroll
                for (int b = 0; b < 4; b++)
                    s[a][b] = fmaf(qv[a], kv[b], s[a][b]);
        }
        #pragma unroll
        for (int a = 0; a < 4; a++)
            *(float4*)&S[(i0 + a) * SST + j0] =
                make_float4(s[a][0], s[a][1], s[a][2], s[a][3]);
    }
    __syncthreads();   // qt dead from here; union region becomes v

    // ---- stage v (into union) + softmax (independent work, one phase) ----
    for (int e = tid; e < 100 * 32; e += 256) {
        int i = e >> 5, d = e & 31;
        v[i * VSTR + d] = (i < NN) ? base[(size_t)i * (3 * CC) + 2 * CC + d] : 0.0f;
    }

    int warp = tid >> 5, lane = tid & 31;
    for (int i = warp; i < NN; i += 8) {
        int li = labs[i];
        float mx = -1e30f;
        for (int j = lane; j < NN; j += 32) {
            float val = S[i * SST + j] + ((labs[j] == li) ? 0.0f : -100.0f);
            S[i * SST + j] = val;
            mx = fmaxf(mx, val);
        }
        #pragma unroll
        for (int o = 16; o; o >>= 1) mx = fmaxf(mx, __shfl_xor_sync(0xffffffffu, mx, o));
        float sum = 0.0f;
        for (int j = lane; j < NN; j += 32) {
            float ev = __expf(S[i * SST + j] - mx);
            S[i * SST + j] = ev;
            sum += ev;
        }
        #pragma unroll
        for (int o = 16; o; o >>= 1) sum += __shfl_xor_sync(0xffffffffu, sum, o);
        float inv = 1.0f / sum;
        for (int j = lane; j < NN; j += 32) S[i * SST + j] *= inv;
        // cols 98-99 remain 0 (kt pads were zero, never exp'd) -> PV-safe
    }
    __syncthreads();

    // ---- O = P @ V : 25x8 grid of 4x4 tiles; K=100 in chunks of 4 ----
    for (int u = tid; u < 200; u += 256) {
        int it = u >> 3, dt = u & 7;
        int i0 = it * 4, d0 = dt * 4;
        float o[4][4];
        #pragma unroll
        for (int a = 0; a < 4; a++)
            #pragma unroll
            for (int b = 0; b < 4; b++) o[a][b] = 0.0f;
        #pragma unroll 5
        for (int jc = 0; jc < 25; jc++) {
            int j0 = jc * 4;
            float4 p[4], vv[4];
            #pragma unroll
            for (int a = 0; a < 4; a++)
                p[a] = *(const float4*)&S[(i0 + a) * SST + j0];
            #pragma unroll
            for (int b = 0; b < 4; b++)
                vv[b] = *(const float4*)&v[(j0 + b) * VSTR + d0];
            #pragma unroll
            for (int a = 0; a < 4; a++) {
                o[a][0] = fmaf(p[a].x, vv[0].x, o[a][0]);
                o[a][1] = fmaf(p[a].x, vv[0].y, o[a][1]);
                o[a][2] = fmaf(p[a].x, vv[0].z, o[a][2]);
                o[a][3] = fmaf(p[a].x, vv[0].w, o[a][3]);
                o[a][0] = fmaf(p[a].y, vv[1].x, o[a][0]);
                o[a][1] = fmaf(p[a].y, vv[1].y, o[a][1]);
                o[a][2] = fmaf(p[a].y, vv[1].z, o[a][2]);
                o[a][3] = fmaf(p[a].y, vv[1].w, o[a][3]);
                o[a][0] = fmaf(p[a].z, vv[2].x, o[a][0]);
                o[a][1] = fmaf(p[a].z, vv[2].y, o[a][1]);
                o[a][2] = fmaf(p[a].z, vv[2].z, o[a][2]);
                o[a][3] = fmaf(p[a].z, vv[2].w, o[a][3]);
                o[a][0] = fmaf(p[a].w, vv[3].x, o[a][0]);
                o[a][1] = fmaf(p[a].w, vv[3].y, o[a][1]);
                o[a][2] = fmaf(p[a].w, vv[3].z, o[a][2]);
                o[a][3] = fmaf(p[a].w, vv[3].w, o[a][3]);
            }
        }
        size_t ob = (size_t)(win * NN) * CC + head * HD + d0;
        #pragma unroll
        for (int a = 0; a < 4; a++) {
            int i = i0 + a;
            if (i < NN) {
                *(float4*)&out[ob + (size_t)i * CC] =
                    make_float4(round_tf32(o[a][0]), round_tf32(o[a][1]),
                                round_tf32(o[a][2]), round_tf32(o[a][3]));
            }
        }
    }
}

// ---------------- launch ----------------
extern "C" void kernel_launch(void* const* d_in, const int* in_sizes, int n_in,
                              void* d_out, int out_size) {
    const float* x      = (const float*)d_in[0];
    // d_in[1] = mask_matrix (unused: mask computed analytically)
    const float* n1g    = (const float*)d_in[2];
    const float* n1b    = (const float*)d_in[3];
    const float* qkv_w  = (const float*)d_in[4];
    const float* qkv_b  = (const float*)d_in[5];
    const float* proj_w = (const float*)d_in[6];
    const float* proj_b = (const float*)d_in[7];
    const float* n2g    = (const float*)d_in[8];
    const float* n2b    = (const float*)d_in[9];
    const float* fc1_w  = (const float*)d_in[10];
    const float* fc1_b  = (const float*)d_in[11];
    const float* fc2_w  = (const float*)d_in[12];
    const float* fc2_b  = (const float*)d_in[13];
    float* out = (float*)d_out;

    float *xw, *qkvb, *ao, *x1, *h2, *hid, *wr;
    cudaGetSymbolAddress((void**)&xw,   g_xw);
    cudaGetSymbolAddress((void**)&qkvb, g_qkv);
    cudaGetSymbolAddress((void**)&ao,   g_ao);
    cudaGetSymbolAddress((void**)&x1,   g_x1);
    cudaGetSymbolAddress((void**)&h2,   g_h2);
    cudaGetSymbolAddress((void**)&hid,  g_hid);
    cudaGetSymbolAddress((void**)&wr,   g_wr);

    cudaFuncSetAttribute(attn_kernel, cudaFuncAttributeMaxDynamicSharedMemorySize,
                         ATTN_SMEM);

    const int mtiles = TT / GBM;   // 1568

    // 0) round weights to tf32 (tiny)
    round_weights_kernel<<<(WTOT + 255) / 256, 256>>>(qkv_w, proj_w, fc1_w, fc2_w, wr);
    // 1) LN1 + shift + window partition (tf32-rounded out)
    ln_kernel<<<TT / 4, 128>>>(x, n1g, n1b, xw, 1);
    // 2) qkv = xw @ qkv_w^T + qkv_b   (N=288)
    gemm_kernel<0><<<dim3(5, mtiles), 256>>>(xw, wr + WQKV_OFF, qkv_b, qkvb, nullptr,
                                             TT, 3 * CC, CC);
    // 3) windowed attention (scalar 4x4 float4, analytic mask, 3 CTAs/SM)
    attn_kernel<<<BW * HEADS, 256, ATTN_SMEM>>>(qkvb, ao);
    // 4) proj + window reverse + unshift + residual(x) -> x1
    gemm_kernel<1><<<dim3(2, mtiles), 256>>>(ao, wr + WPROJ_OFF, proj_b, x1, x,
                                             TT, CC, CC);
    // 5) LN2 (tf32-rounded out)
    ln_kernel<<<TT / 4, 128>>>(x1, n2g, n2b, h2, 0);
    // 6) fc1 + exact GELU (tf32-rounded out)
    gemm_kernel<2><<<dim3(6, mtiles), 256>>>(h2, wr + WFC1_OFF, fc1_b, hid, nullptr,
                                             TT, HID, CC);
    // 7) fc2 + residual(x1) -> out
    gemm_kernel<3><<<dim3(2, mtiles), 256>>>(hid, wr + WFC2_OFF, fc2_b, out, x1,
                                             TT, CC, HID);
}

// round 13
// speedup vs baseline: 2.0871x; 1.0886x over previous
#include <cuda_runtime.h>
#include <cstdint>
#include <cstdio>

// ---------------- problem constants ----------------
#define BB   2
#define DD   32
#define HH   56
#define WW   56
#define CC   96
#define HEADS 3
#define HD   32
#define NN   98          // window tokens = 2*7*7
#define NWIN 1024        // windows per batch = 16*8*8
#define BW   (BB*NWIN)   // 2048 windows
#define TT   (BW*NN)     // 200704 tokens
#define HID  384

// ---------------- scratch (device globals; allocation-free) ----------------
__device__ float g_xw  [(size_t)TT*CC];     // LN1 out (tf32-rounded)
__device__ float g_qkv [(size_t)TT*3*CC];
__device__ float g_ao  [(size_t)TT*CC];     // attn out (tf32-rounded)
__device__ float g_x1  [(size_t)TT*CC];
__device__ float g_h2  [(size_t)TT*CC];     // LN2 out (tf32-rounded)
__device__ float g_hid [(size_t)TT*HID];    // gelu out (tf32-rounded)

// rounded weights: qkv | proj | fc1 | fc2
#define WQKV_OFF 0
#define WPROJ_OFF 27648
#define WFC1_OFF 36864
#define WFC2_OFF 73728
#define WTOT     110592
__device__ float g_wr[WTOT];

__device__ __forceinline__ uint32_t cvt_tf32(float x) {
    uint32_t r;
    asm("cvt.rna.tf32.f32 %0, %1;" : "=r"(r) : "f"(x));
    return r;
}
__device__ __forceinline__ float round_tf32(float x) {
    return __uint_as_float(cvt_tf32(x));
}

// Map window-token index -> spatial token index (shifted gather/scatter).
__device__ __forceinline__ int win_to_spatial(int t) {
    int win = t / NN, n = t - win * NN;
    int b  = win >> 10;
    int wi = win & 1023;
    int d0 = wi >> 6, h0 = (wi >> 3) & 7, w0 = wi & 7;
    int dd = n / 49;  int r = n - dd * 49;
    int hh = r / 7;   int ww = r - hh * 7;
    int d = d0 * 2 + dd + 1; if (d >= DD) d -= DD;
    int h = h0 * 7 + hh + 3; if (h >= HH) h -= HH;
    int w = w0 * 7 + ww + 3; if (w >= WW) w -= WW;
    return ((b * DD + d) * HH + h) * WW + w;
}

// ---------------- weight rounding (one-shot, tiny) ----------------
__global__ void round_weights_kernel(const float* __restrict__ qkv_w,
                                     const float* __restrict__ proj_w,
                                     const float* __restrict__ fc1_w,
                                     const float* __restrict__ fc2_w,
                                     float* __restrict__ wr) {
    int i = blockIdx.x * 256 + threadIdx.x;
    if (i < WTOT) {
        float v;
        if      (i < WPROJ_OFF) v = qkv_w[i - WQKV_OFF];
        else if (i < WFC1_OFF)  v = proj_w[i - WPROJ_OFF];
        else if (i < WFC2_OFF)  v = fc1_w[i - WFC1_OFF];
        else                    v = fc2_w[i - WFC2_OFF];
        wr[i] = round_tf32(v);
    }
}

// ---------------- LayerNorm (warp per token, C=96=3*32), tf32-rounded out ----
__global__ void ln_kernel(const float* __restrict__ in,
                          const float* __restrict__ g,
                          const float* __restrict__ bta,
                          float* __restrict__ out, int gather) {
    int t = blockIdx.x * 4 + (threadIdx.x >> 5);
    int lane = threadIdx.x & 31;
    size_t src = gather ? (size_t)win_to_spatial(t) * CC : (size_t)t * CC;
    float x0 = in[src + lane];
    float x1 = in[src + lane + 32];
    float x2 = in[src + lane + 64];
    float s  = x0 + x1 + x2;
    float sq = x0 * x0 + x1 * x1 + x2 * x2;
    #pragma unroll
    for (int o = 16; o; o >>= 1) {
        s  += __shfl_xor_sync(0xffffffffu, s,  o);
        sq += __shfl_xor_sync(0xffffffffu, sq, o);
    }
    float mean = s * (1.0f / 96.0f);
    float var  = sq * (1.0f / 96.0f) - mean * mean;
    float rst  = rsqrtf(var + 1e-5f);
    size_t dst = (size_t)t * CC;
    out[dst + lane]      = round_tf32((x0 - mean) * rst * g[lane]      + bta[lane]);
    out[dst + lane + 32] = round_tf32((x1 - mean) * rst * g[lane + 32] + bta[lane + 32]);
    out[dst + lane + 64] = round_tf32((x2 - mean) * rst * g[lane + 64] + bta[lane + 64]);
}

// ---------------- shared mma helper (GEMMs only) ----------------
__device__ __forceinline__ void mma_tf32(float* d, const uint32_t* a, const uint32_t* b) {
    asm volatile(
        "mma.sync.aligned.m16n8k8.row.col.f32.tf32.tf32.f32 "
        "{%0,%1,%2,%3}, {%4,%5,%6,%7}, {%8,%9}, {%0,%1,%2,%3};\n"
        : "+f"(d[0]), "+f"(d[1]), "+f"(d[2]), "+f"(d[3])
        : "r"(a[0]), "r"(a[1]), "r"(a[2]), "r"(a[3]),
          "r"(b[0]), "r"(b[1]));
}

// ---------------- tf32 tensor-core GEMM: C[M,Nd] = A[M,K] * W[Nd,K]^T + bias ----
#define GBM 128
#define GBN 64
#define GBK 32
#define SSTR 36

__device__ __forceinline__ void cp16(uint32_t dst_smem, const float* src, bool pred) {
    int sz = pred ? 16 : 0;
    asm volatile("cp.async.ca.shared.global [%0], [%1], 16, %2;\n"
                 :: "r"(dst_smem), "l"(src), "r"(sz));
}

template<int EPI>
__global__ void __launch_bounds__(256)
gemm_kernel(const float* __restrict__ A, const float* __restrict__ Wt,
            const float* __restrict__ bias, float* __restrict__ Cout,
            const float* __restrict__ res, int M, int Nd, int K) {
    __shared__ float As[2][GBM * SSTR];
    __shared__ float Bs[2][GBN * SSTR];

    int tid  = threadIdx.x;
    int lane = tid & 31, warp = tid >> 5;
    int wm = warp >> 1;
    int wn = warp & 1;
    int g  = lane >> 2, l4 = lane & 3;
    int mBase = blockIdx.y * GBM;
    int nBase = blockIdx.x * GBN;

    int lr = tid >> 3;
    int lc = (tid & 7) * 4;

    const float* Ap = A + (size_t)(mBase + lr) * K + lc;
    const float* Bp = Wt + (size_t)(nBase + lr) * K + lc;

    uint32_t asb = (uint32_t)__cvta_generic_to_shared(&As[0][0]);
    uint32_t bsb = (uint32_t)__cvta_generic_to_shared(&Bs[0][0]);

    float acc[2][4][4];
    #pragma unroll
    for (int mt = 0; mt < 2; mt++)
        #pragma unroll
        for (int nt = 0; nt < 4; nt++)
            #pragma unroll
            for (int e = 0; e < 4; e++) acc[mt][nt][e] = 0.0f;

    int nTiles = K / GBK;

    auto prefetch = [&](int s, int kt) {
        uint32_t ad = asb + (uint32_t)(s * GBM * SSTR + lr * SSTR + lc) * 4;
        uint32_t bd = bsb + (uint32_t)(s * GBN * SSTR + lr * SSTR + lc) * 4;
        int kb = kt * GBK;
        #pragma unroll
        for (int i = 0; i < 4; i++)
            cp16(ad + i * 32 * SSTR * 4, Ap + (size_t)i * 32 * K + kb, true);
        #pragma unroll
        for (int i = 0; i < 2; i++)
            cp16(bd + i * 32 * SSTR * 4, Bp + (size_t)i * 32 * K + kb,
                 (nBase + lr + i * 32) < Nd);
        asm volatile("cp.async.commit_group;\n" ::);
    };

    prefetch(0, 0);
    prefetch(1, 1);

    for (int kt = 0; kt < nTiles; kt++) {
        if (kt + 1 < nTiles)
            asm volatile("cp.async.wait_group 1;\n" ::);
        else
            asm volatile("cp.async.wait_group 0;\n" ::);
        __syncthreads();

        int s = kt & 1;
        const float* as = As[s];
        const float* bs = Bs[s];

        #pragma unroll
        for (int kk = 0; kk < GBK; kk += 8) {
            int kq = kk + l4;
            uint32_t af[2][4], bf[4][2];
            #pragma unroll
            for (int mt = 0; mt < 2; mt++) {
                int r = wm * 32 + mt * 16 + g;
                af[mt][0] = __float_as_uint(as[r * SSTR + kq]);
                af[mt][1] = __float_as_uint(as[(r + 8) * SSTR + kq]);
                af[mt][2] = __float_as_uint(as[r * SSTR + kq + 4]);
                af[mt][3] = __float_as_uint(as[(r + 8) * SSTR + kq + 4]);
            }
            #pragma unroll
            for (int nt = 0; nt < 4; nt++) {
                int c = wn * 32 + nt * 8 + g;
                bf[nt][0] = __float_as_uint(bs[c * SSTR + kq]);
                bf[nt][1] = __float_as_uint(bs[c * SSTR + kq + 4]);
            }
            #pragma unroll
            for (int mt = 0; mt < 2; mt++)
                #pragma unroll
                for (int nt = 0; nt < 4; nt++)
                    mma_tf32(acc[mt][nt], af[mt], bf[nt]);
        }
        __syncthreads();
        if (kt + 2 < nTiles) prefetch(s, kt + 2);
    }

    #pragma unroll
    for (int mt = 0; mt < 2; mt++) {
        #pragma unroll
        for (int h = 0; h < 2; h++) {
            int m = mBase + wm * 32 + mt * 16 + g + h * 8;
            size_t dstrow;
            if (EPI == 1) dstrow = (size_t)win_to_spatial(m) * Nd;
            else          dstrow = (size_t)m * Nd;
            #pragma unroll
            for (int nt = 0; nt < 4; nt++) {
                #pragma unroll
                for (int e = 0; e < 2; e++) {
                    int n = nBase + wn * 32 + nt * 8 + 2 * l4 + e;
                    if (n < Nd) {
                        float v = acc[mt][nt][h * 2 + e] + bias[n];
                        if (EPI == 0) {
                            Cout[dstrow + n] = v;
                        } else if (EPI == 1) {
                            Cout[dstrow + n] = res[dstrow + n] + v;
                        } else if (EPI == 2) {
                            float gl = 0.5f * v * (1.0f + erff(v * 0.70710678118654752f));
                            Cout[dstrow + n] = round_tf32(gl);
                        } else {
                            Cout[dstrow + n] = res[dstrow + n] + v;
                        }
                    }
                }
            }
        }
    }
}

// ---------------- scalar windowed attention, float4 4x4 tiles + analytic mask --
// Block per (window, head), 320 threads (10 warps), 68.5 KB smem -> 3 CTAs/SM.
// Softmax: SINGLE pass (no max-shift — scores tiny; masked -> exact 0),
// 1/sum deferred to PV epilogue via rsinv[] row array.
// smem floats: kt[32][104] | union{qt[32][104], v[100][36]} | S[100][100]
//              | labs[104] int | rsinv[100]
#define ATHREADS 320
#define AWARPS   10
#define AKT_OFF 0
#define AUN_OFF 3328                   // qt (3328 floats) / v (3600 floats)
#define AS_OFF  (AUN_OFF + 3600)       // 6928
#define ALAB_OFF (AS_OFF + 10000)      // 16928
#define ARS_OFF  (ALAB_OFF + 104)      // 17032
#define VSTR 36
#define QSTR 104
#define SST  100
#define ATTN_SMEM ((17032 + 100) * 4)  // 68528 B

__device__ __forceinline__ int region3(int c, int lo, int hi) {
    return (c >= lo) + (c >= hi);
}

__global__ void __launch_bounds__(ATHREADS)
attn_kernel(const float* __restrict__ qkv, float* __restrict__ out) {
    int blk  = blockIdx.x;
    int win  = blk / HEADS;
    int head = blk - win * HEADS;
    int wi   = win & 1023;
    extern __shared__ float sm[];
    float* kt = sm + AKT_OFF;
    float* qt = sm + AUN_OFF;      // union with v
    float* v  = sm + AUN_OFF;
    float* S  = sm + AS_OFF;
    int*  labs  = (int*)(sm + ALAB_OFF);
    float* rsinv = sm + ARS_OFF;
    int tid = threadIdx.x;
    const float scale = 0.17677669529663687f;

    const float* base = qkv + (size_t)(win * NN) * (3 * CC) + head * HD;

    // region labels from window coords (mask analytic; no gmem mask)
    if (tid < NN) {
        int d0 = wi >> 6, h0 = (wi >> 3) & 7, w0 = wi & 7;
        int dd = tid / 49; int r = tid - dd * 49;
        int hh = r / 7;    int ww = r - hh * 7;
        int d = d0 * 2 + dd;
        int h = h0 * 7 + hh;
        int w = w0 * 7 + ww;
        labs[tid] = region3(d, DD - 2, DD - 1) * 9
                  + region3(h, HH - 7, HH - 3) * 3
                  + region3(w, WW - 7, WW - 3);
    } else if (tid < 100) {
        rsinv[tid] = 0.0f;   // pad rows (results discarded, keep finite)
    }

    // stage q^T, k^T (coalesced gmem reads, transposed smem writes), zero pads
    for (int e = tid; e < 104 * 32; e += ATHREADS) {
        int i = e >> 5, d = e & 31;
        qt[d * QSTR + i] = (i < NN) ? base[(size_t)i * (3 * CC) + d] * scale : 0.0f;
        kt[d * QSTR + i] = (i < NN) ? base[(size_t)i * (3 * CC) + CC + d] : 0.0f;
    }
    __syncthreads();

    // ---- S = q k^T : 25x25 grid of 4x4 tiles (max 2 waves/thread @320) ----
    for (int u = tid; u < 625; u += ATHREADS) {
        int it = u / 25, jt = u - it * 25;
        int i0 = it * 4, j0 = jt * 4;
        float s[4][4];
        #pragma unroll
        for (int a = 0; a < 4; a++)
            #pragma unroll
            for (int b = 0; b < 4; b++) s[a][b] = 0.0f;
        #pragma unroll 8
        for (int d = 0; d < 32; d++) {
            float4 qa = *(const float4*)&qt[d * QSTR + i0];
            float4 kb = *(const float4*)&kt[d * QSTR + j0];
            float qv[4] = {qa.x, qa.y, qa.z, qa.w};
            float kv[4] = {kb.x, kb.y, kb.z, kb.w};
            #pragma unroll
            for (int a = 0; a < 4; a++)
                #pragma unroll
                for (int b = 0; b < 4; b++)
                    s[a][b] = fmaf(qv[a], kv[b], s[a][b]);
        }
        #pragma unroll
        for (int a = 0; a < 4; a++)
            *(float4*)&S[(i0 + a) * SST + j0] =
                make_float4(s[a][0], s[a][1], s[a][2], s[a][3]);
    }
    __syncthreads();   // qt dead from here; union region becomes v

    // ---- stage v (into union) + single-pass softmax ----
    for (int e = tid; e < 100 * 32; e += ATHREADS) {
        int i = e >> 5, d = e & 31;
        v[i * VSTR + d] = (i < NN) ? base[(size_t)i * (3 * CC) + 2 * CC + d] : 0.0f;
    }

    int warp = tid >> 5, lane = tid & 31;
    for (int i = warp; i < NN; i += AWARPS) {
        int li = labs[i];
        float sum = 0.0f;
        // no max-shift: |scores| << 88, exp is safe; masked -> exact 0
        for (int j = lane; j < NN; j += 32) {
            float ev = (labs[j] == li) ? __expf(S[i * SST + j]) : 0.0f;
            S[i * SST + j] = ev;
            sum += ev;
        }
        #pragma unroll
        for (int o = 16; o; o >>= 1) sum += __shfl_xor_sync(0xffffffffu, sum, o);
        if (lane == 0) rsinv[i] = 1.0f / sum;
        // cols 98-99 remain 0 (kt pads zero -> raw S=0 there, never exp'd... they
        // hold raw 0.0 which is exactly the padded-P value needed) -> PV-safe
    }
    __syncthreads();

    // ---- O = (P @ V) * rsinv : 25x8 grid of 4x4 tiles; K=100 chunks of 4 ----
    for (int u = tid; u < 200; u += ATHREADS) {
        int it = u >> 3, dt = u & 7;
        int i0 = it * 4, d0 = dt * 4;
        float o[4][4];
        #pragma unroll
        for (int a = 0; a < 4; a++)
            #pragma unroll
            for (int b = 0; b < 4; b++) o[a][b] = 0.0f;
        #pragma unroll 5
        for (int jc = 0; jc < 25; jc++) {
            int j0 = jc * 4;
            float4 p[4], vv[4];
            #pragma unroll
            for (int a = 0; a < 4; a++)
                p[a] = *(const float4*)&S[(i0 + a) * SST + j0];
            #pragma unroll
            for (int b = 0; b < 4; b++)
                vv[b] = *(const float4*)&v[(j0 + b) * VSTR + d0];
            #pragma unroll
            for (int a = 0; a < 4; a++) {
                o[a][0] = fmaf(p[a].x, vv[0].x, o[a][0]);
                o[a][1] = fmaf(p[a].x, vv[0].y, o[a][1]);
                o[a][2] = fmaf(p[a].x, vv[0].z, o[a][2]);
                o[a][3] = fmaf(p[a].x, vv[0].w, o[a][3]);
                o[a][0] = fmaf(p[a].y, vv[1].x, o[a][0]);
                o[a][1] = fmaf(p[a].y, vv[1].y, o[a][1]);
                o[a][2] = fmaf(p[a].y, vv[1].z, o[a][2]);
                o[a][3] = fmaf(p[a].y, vv[1].w, o[a][3]);
                o[a][0] = fmaf(p[a].z, vv[2].x, o[a][0]);
                o[a][1] = fmaf(p[a].z, vv[2].y, o[a][1]);
                o[a][2] = fmaf(p[a].z, vv[2].z, o[a][2]);
                o[a][3] = fmaf(p[a].z, vv[2].w, o[a][3]);
                o[a][0] = fmaf(p[a].w, vv[3].x, o[a][0]);
                o[a][1] = fmaf(p[a].w, vv[3].y, o[a][1]);
                o[a][2] = fmaf(p[a].w, vv[3].z, o[a][2]);
                o[a][3] = fmaf(p[a].w, vv[3].w, o[a][3]);
            }
        }
        size_t ob = (size_t)(win * NN) * CC + head * HD + d0;
        #pragma unroll
        for (int a = 0; a < 4; a++) {
            int i = i0 + a;
            if (i < NN) {
                float rs = rsinv[i];
                *(float4*)&out[ob + (size_t)i * CC] =
                    make_float4(round_tf32(o[a][0] * rs), round_tf32(o[a][1] * rs),
                                round_tf32(o[a][2] * rs), round_tf32(o[a][3] * rs));
            }
        }
    }
}

// ---------------- launch ----------------
extern "C" void kernel_launch(void* const* d_in, const int* in_sizes, int n_in,
                              void* d_out, int out_size) {
    const float* x      = (const float*)d_in[0];
    // d_in[1] = mask_matrix (unused: mask computed analytically)
    const float* n1g    = (const float*)d_in[2];
    const float* n1b    = (const float*)d_in[3];
    const float* qkv_w  = (const float*)d_in[4];
    const float* qkv_b  = (const float*)d_in[5];
    const float* proj_w = (const float*)d_in[6];
    const float* proj_b = (const float*)d_in[7];
    const float* n2g    = (const float*)d_in[8];
    const float* n2b    = (const float*)d_in[9];
    const float* fc1_w  = (const float*)d_in[10];
    const float* fc1_b  = (const float*)d_in[11];
    const float* fc2_w  = (const float*)d_in[12];
    const float* fc2_b  = (const float*)d_in[13];
    float* out = (float*)d_out;

    float *xw, *qkvb, *ao, *x1, *h2, *hid, *wr;
    cudaGetSymbolAddress((void**)&xw,   g_xw);
    cudaGetSymbolAddress((void**)&qkvb, g_qkv);
    cudaGetSymbolAddress((void**)&ao,   g_ao);
    cudaGetSymbolAddress((void**)&x1,   g_x1);
    cudaGetSymbolAddress((void**)&h2,   g_h2);
    cudaGetSymbolAddress((void**)&hid,  g_hid);
    cudaGetSymbolAddress((void**)&wr,   g_wr);

    cudaFuncSetAttribute(attn_kernel, cudaFuncAttributeMaxDynamicSharedMemorySize,
                         ATTN_SMEM);

    const int mtiles = TT / GBM;   // 1568

    // 0) round weights to tf32 (tiny)
    round_weights_kernel<<<(WTOT + 255) / 256, 256>>>(qkv_w, proj_w, fc1_w, fc2_w, wr);
    // 1) LN1 + shift + window partition (tf32-rounded out)
    ln_kernel<<<TT / 4, 128>>>(x, n1g, n1b, xw, 1);
    // 2) qkv = xw @ qkv_w^T + qkv_b   (N=288)
    gemm_kernel<0><<<dim3(5, mtiles), 256>>>(xw, wr + WQKV_OFF, qkv_b, qkvb, nullptr,
                                             TT, 3 * CC, CC);
    // 3) windowed attention (single-pass softmax, deferred norm, 320 thr)
    attn_kernel<<<BW * HEADS, ATHREADS, ATTN_SMEM>>>(qkvb, ao);
    // 4) proj + window reverse + unshift + residual(x) -> x1
    gemm_kernel<1><<<dim3(2, mtiles), 256>>>(ao, wr + WPROJ_OFF, proj_b, x1, x,
                                             TT, CC, CC);
    // 5) LN2 (tf32-rounded out)
    ln_kernel<<<TT / 4, 128>>>(x1, n2g, n2b, h2, 0);
    // 6) fc1 + exact GELU (tf32-rounded out)
    gemm_kernel<2><<<dim3(6, mtiles), 256>>>(h2, wr + WFC1_OFF, fc1_b, hid, nullptr,
                                             TT, HID, CC);
    // 7) fc2 + residual(x1) -> out
    gemm_kernel<3><<<dim3(2, mtiles), 256>>>(hid, wr + WFC2_OFF, fc2_b, out, x1,
                                             TT, CC, HID);
}

// round 14
// speedup vs baseline: 2.3254x; 1.1142x over previous
#include <cuda_runtime.h>
#include <cstdint>
#include <cstdio>

// ---------------- problem constants ----------------
#define BB   2
#define DD   32
#define HH   56
#define WW   56
#define CC   96
#define HEADS 3
#define HD   32
#define NN   98          // window tokens = 2*7*7
#define NWIN 1024        // windows per batch = 16*8*8
#define BW   (BB*NWIN)   // 2048 windows
#define TT   (BW*NN)     // 200704 tokens
#define HID  384

// ---------------- scratch (device globals; allocation-free) ----------------
__device__ float g_xw  [(size_t)TT*CC];     // LN1 out (tf32-rounded)
__device__ float g_qkv [(size_t)TT*3*CC];
__device__ float g_ao  [(size_t)TT*CC];     // attn out (tf32-rounded)
__device__ float g_x1  [(size_t)TT*CC];
__device__ float g_h2  [(size_t)TT*CC];     // LN2 out (tf32-rounded)
__device__ float g_hid [(size_t)TT*HID];    // gelu out (tf32-rounded)

// rounded weights: qkv | proj | fc1 | fc2
#define WQKV_OFF 0
#define WPROJ_OFF 27648
#define WFC1_OFF 36864
#define WFC2_OFF 73728
#define WTOT     110592
__device__ float g_wr[WTOT];

__device__ __forceinline__ uint32_t cvt_tf32(float x) {
    uint32_t r;
    asm("cvt.rna.tf32.f32 %0, %1;" : "=r"(r) : "f"(x));
    return r;
}
__device__ __forceinline__ float round_tf32(float x) {
    return __uint_as_float(cvt_tf32(x));
}

// Map window-token index -> spatial token index (shifted gather/scatter).
__device__ __forceinline__ int win_to_spatial(int t) {
    int win = t / NN, n = t - win * NN;
    int b  = win >> 10;
    int wi = win & 1023;
    int d0 = wi >> 6, h0 = (wi >> 3) & 7, w0 = wi & 7;
    int dd = n / 49;  int r = n - dd * 49;
    int hh = r / 7;   int ww = r - hh * 7;
    int d = d0 * 2 + dd + 1; if (d >= DD) d -= DD;
    int h = h0 * 7 + hh + 3; if (h >= HH) h -= HH;
    int w = w0 * 7 + ww + 3; if (w >= WW) w -= WW;
    return ((b * DD + d) * HH + h) * WW + w;
}

// ---------------- weight rounding (one-shot, tiny) ----------------
__global__ void round_weights_kernel(const float* __restrict__ qkv_w,
                                     const float* __restrict__ proj_w,
                                     const float* __restrict__ fc1_w,
                                     const float* __restrict__ fc2_w,
                                     float* __restrict__ wr) {
    int i = blockIdx.x * 256 + threadIdx.x;
    if (i < WTOT) {
        float v;
        if      (i < WPROJ_OFF) v = qkv_w[i - WQKV_OFF];
        else if (i < WFC1_OFF)  v = proj_w[i - WPROJ_OFF];
        else if (i < WFC2_OFF)  v = fc1_w[i - WFC1_OFF];
        else                    v = fc2_w[i - WFC2_OFF];
        wr[i] = round_tf32(v);
    }
}

// ---------------- LayerNorm (warp per token, C=96=3*32), tf32-rounded out ----
__global__ void ln_kernel(const float* __restrict__ in,
                          const float* __restrict__ g,
                          const float* __restrict__ bta,
                          float* __restrict__ out, int gather) {
    int t = blockIdx.x * 4 + (threadIdx.x >> 5);
    int lane = threadIdx.x & 31;
    size_t src = gather ? (size_t)win_to_spatial(t) * CC : (size_t)t * CC;
    float x0 = in[src + lane];
    float x1 = in[src + lane + 32];
    float x2 = in[src + lane + 64];
    float s  = x0 + x1 + x2;
    float sq = x0 * x0 + x1 * x1 + x2 * x2;
    #pragma unroll
    for (int o = 16; o; o >>= 1) {
        s  += __shfl_xor_sync(0xffffffffu, s,  o);
        sq += __shfl_xor_sync(0xffffffffu, sq, o);
    }
    float mean = s * (1.0f / 96.0f);
    float var  = sq * (1.0f / 96.0f) - mean * mean;
    float rst  = rsqrtf(var + 1e-5f);
    size_t dst = (size_t)t * CC;
    out[dst + lane]      = round_tf32((x0 - mean) * rst * g[lane]      + bta[lane]);
    out[dst + lane + 32] = round_tf32((x1 - mean) * rst * g[lane + 32] + bta[lane + 32]);
    out[dst + lane + 64] = round_tf32((x2 - mean) * rst * g[lane + 64] + bta[lane + 64]);
}

// ---------------- shared mma helper (GEMMs only) ----------------
__device__ __forceinline__ void mma_tf32(float* d, const uint32_t* a, const uint32_t* b) {
    asm volatile(
        "mma.sync.aligned.m16n8k8.row.col.f32.tf32.tf32.f32 "
        "{%0,%1,%2,%3}, {%4,%5,%6,%7}, {%8,%9}, {%0,%1,%2,%3};\n"
        : "+f"(d[0]), "+f"(d[1]), "+f"(d[2]), "+f"(d[3])
        : "r"(a[0]), "r"(a[1]), "r"(a[2]), "r"(a[3]),
          "r"(b[0]), "r"(b[1]));
}

// ---------------- tf32 tensor-core GEMM: C[M,Nd] = A[M,K] * W[Nd,K]^T + bias ----
// BM=128, BN=96 (all Nd are multiples of 96 -> zero waste, no predicates),
// BK=32; 256 threads = 8 warps (4m x 2n), warp tile 32x48 (acc[2][6][4]).
// Dynamic smem (64.5 KB, double-buffered), cp.async. 3 CTAs/SM via
// __launch_bounds__(256,3). Per k8-step: 20 LDS.32 / 12 MMA.
#define GBM 128
#define GBN 96
#define GBK 32
#define SSTR 36
#define AS_TILE (GBM * SSTR)          // 4608 floats
#define BS_TILE (GBN * SSTR)          // 3456 floats
#define BS_BASE (2 * AS_TILE)         // 9216
#define GEMM_SMEM ((2 * AS_TILE + 2 * BS_TILE) * 4)   // 64512 B

__device__ __forceinline__ void cp16(uint32_t dst_smem, const float* src) {
    asm volatile("cp.async.ca.shared.global [%0], [%1], 16;\n"
                 :: "r"(dst_smem), "l"(src));
}

template<int EPI>
__global__ void __launch_bounds__(256, 3)
gemm_kernel(const float* __restrict__ A, const float* __restrict__ Wt,
            const float* __restrict__ bias, float* __restrict__ Cout,
            const float* __restrict__ res, int M, int Nd, int K) {
    extern __shared__ float gsm[];

    int tid  = threadIdx.x;
    int lane = tid & 31, warp = tid >> 5;
    int wm = warp >> 1;          // 0..3  (32-row slice)
    int wn = warp & 1;           // 0..1  (48-col slice)
    int g  = lane >> 2, l4 = lane & 3;
    int mBase = blockIdx.y * GBM;
    int nBase = blockIdx.x * GBN;

    int lr = tid >> 3;           // 0..31
    int lc = (tid & 7) * 4;      // 0,4,..28

    const float* Ap = A + (size_t)(mBase + lr) * K + lc;
    const float* Bp = Wt + (size_t)(nBase + lr) * K + lc;

    uint32_t smb = (uint32_t)__cvta_generic_to_shared(gsm);

    float acc[2][6][4];
    #pragma unroll
    for (int mt = 0; mt < 2; mt++)
        #pragma unroll
        for (int nt = 0; nt < 6; nt++)
            #pragma unroll
            for (int e = 0; e < 4; e++) acc[mt][nt][e] = 0.0f;

    int nTiles = K / GBK;

    auto prefetch = [&](int s, int kt) {
        uint32_t ad = smb + (uint32_t)(s * AS_TILE + lr * SSTR + lc) * 4;
        uint32_t bd = smb + (uint32_t)(BS_BASE + s * BS_TILE + lr * SSTR + lc) * 4;
        int kb = kt * GBK;
        #pragma unroll
        for (int i = 0; i < 4; i++)
            cp16(ad + i * 32 * SSTR * 4, Ap + (size_t)i * 32 * K + kb);
        #pragma unroll
        for (int i = 0; i < 3; i++)
            cp16(bd + i * 32 * SSTR * 4, Bp + (size_t)i * 32 * K + kb);
        asm volatile("cp.async.commit_group;\n" ::);
    };

    prefetch(0, 0);
    prefetch(1, 1);

    for (int kt = 0; kt < nTiles; kt++) {
        if (kt + 1 < nTiles)
            asm volatile("cp.async.wait_group 1;\n" ::);
        else
            asm volatile("cp.async.wait_group 0;\n" ::);
        __syncthreads();

        int s = kt & 1;
        const float* as = gsm + s * AS_TILE;
        const float* bs = gsm + BS_BASE + s * BS_TILE;

        #pragma unroll
        for (int kk = 0; kk < GBK; kk += 8) {
            int kq = kk + l4;
            uint32_t af[2][4], bf[6][2];
            #pragma unroll
            for (int mt = 0; mt < 2; mt++) {
                int r = wm * 32 + mt * 16 + g;
                af[mt][0] = __float_as_uint(as[r * SSTR + kq]);
                af[mt][1] = __float_as_uint(as[(r + 8) * SSTR + kq]);
                af[mt][2] = __float_as_uint(as[r * SSTR + kq + 4]);
                af[mt][3] = __float_as_uint(as[(r + 8) * SSTR + kq + 4]);
            }
            #pragma unroll
            for (int nt = 0; nt < 6; nt++) {
                int c = wn * 48 + nt * 8 + g;
                bf[nt][0] = __float_as_uint(bs[c * SSTR + kq]);
                bf[nt][1] = __float_as_uint(bs[c * SSTR + kq + 4]);
            }
            #pragma unroll
            for (int mt = 0; mt < 2; mt++)
                #pragma unroll
                for (int nt = 0; nt < 6; nt++)
                    mma_tf32(acc[mt][nt], af[mt], bf[nt]);
        }
        __syncthreads();
        if (kt + 2 < nTiles) prefetch(s, kt + 2);
    }

    // epilogue (Nd multiple of 96 -> no n bounds checks)
    #pragma unroll
    for (int mt = 0; mt < 2; mt++) {
        #pragma unroll
        for (int h = 0; h < 2; h++) {
            int m = mBase + wm * 32 + mt * 16 + g + h * 8;
            size_t dstrow;
            if (EPI == 1) dstrow = (size_t)win_to_spatial(m) * Nd;
            else          dstrow = (size_t)m * Nd;
            #pragma unroll
            for (int nt = 0; nt < 6; nt++) {
                #pragma unroll
                for (int e = 0; e < 2; e++) {
                    int n = nBase + wn * 48 + nt * 8 + 2 * l4 + e;
                    float v = acc[mt][nt][h * 2 + e] + bias[n];
                    if (EPI == 0) {
                        Cout[dstrow + n] = v;
                    } else if (EPI == 1) {
                        Cout[dstrow + n] = res[dstrow + n] + v;
                    } else if (EPI == 2) {
                        float gl = 0.5f * v * (1.0f + erff(v * 0.70710678118654752f));
                        Cout[dstrow + n] = round_tf32(gl);
                    } else {
                        Cout[dstrow + n] = res[dstrow + n] + v;
                    }
                }
            }
        }
    }
}

// ---------------- scalar windowed attention (unchanged from R13) -------------
#define ATHREADS 320
#define AWARPS   10
#define AKT_OFF 0
#define AUN_OFF 3328                   // qt (3328 floats) / v (3600 floats)
#define AS_OFF  (AUN_OFF + 3600)       // 6928
#define ALAB_OFF (AS_OFF + 10000)      // 16928
#define ARS_OFF  (ALAB_OFF + 104)      // 17032
#define VSTR 36
#define QSTR 104
#define SST  100
#define ATTN_SMEM ((17032 + 100) * 4)  // 68528 B

__device__ __forceinline__ int region3(int c, int lo, int hi) {
    return (c >= lo) + (c >= hi);
}

__global__ void __launch_bounds__(ATHREADS)
attn_kernel(const float* __restrict__ qkv, float* __restrict__ out) {
    int blk  = blockIdx.x;
    int win  = blk / HEADS;
    int head = blk - win * HEADS;
    int wi   = win & 1023;
    extern __shared__ float sm[];
    float* kt = sm + AKT_OFF;
    float* qt = sm + AUN_OFF;      // union with v
    float* v  = sm + AUN_OFF;
    float* S  = sm + AS_OFF;
    int*  labs  = (int*)(sm + ALAB_OFF);
    float* rsinv = sm + ARS_OFF;
    int tid = threadIdx.x;
    const float scale = 0.17677669529663687f;

    const float* base = qkv + (size_t)(win * NN) * (3 * CC) + head * HD;

    if (tid < NN) {
        int d0 = wi >> 6, h0 = (wi >> 3) & 7, w0 = wi & 7;
        int dd = tid / 49; int r = tid - dd * 49;
        int hh = r / 7;    int ww = r - hh * 7;
        int d = d0 * 2 + dd;
        int h = h0 * 7 + hh;
        int w = w0 * 7 + ww;
        labs[tid] = region3(d, DD - 2, DD - 1) * 9
                  + region3(h, HH - 7, HH - 3) * 3
                  + region3(w, WW - 7, WW - 3);
    } else if (tid < 100) {
        rsinv[tid] = 0.0f;
    }

    for (int e = tid; e < 104 * 32; e += ATHREADS) {
        int i = e >> 5, d = e & 31;
        qt[d * QSTR + i] = (i < NN) ? base[(size_t)i * (3 * CC) + d] * scale : 0.0f;
        kt[d * QSTR + i] = (i < NN) ? base[(size_t)i * (3 * CC) + CC + d] : 0.0f;
    }
    __syncthreads();

    for (int u = tid; u < 625; u += ATHREADS) {
        int it = u / 25, jt = u - it * 25;
        int i0 = it * 4, j0 = jt * 4;
        float s[4][4];
        #pragma unroll
        for (int a = 0; a < 4; a++)
            #pragma unroll
            for (int b = 0; b < 4; b++) s[a][b] = 0.0f;
        #pragma unroll 8
        for (int d = 0; d < 32; d++) {
            float4 qa = *(const float4*)&qt[d * QSTR + i0];
            float4 kb = *(const float4*)&kt[d * QSTR + j0];
            float qv[4] = {qa.x, qa.y, qa.z, qa.w};
            float kv[4] = {kb.x, kb.y, kb.z, kb.w};
            #pragma unroll
            for (int a = 0; a < 4; a++)
                #pragma unroll
                for (int b = 0; b < 4; b++)
                    s[a][b] = fmaf(qv[a], kv[b], s[a][b]);
        }
        #pragma unroll
        for (int a = 0; a < 4; a++)
            *(float4*)&S[(i0 + a) * SST + j0] =
                make_float4(s[a][0], s[a][1], s[a][2], s[a][3]);
    }
    __syncthreads();   // qt dead from here; union region becomes v

    for (int e = tid; e < 100 * 32; e += ATHREADS) {
        int i = e >> 5, d = e & 31;
        v[i * VSTR + d] = (i < NN) ? base[(size_t)i * (3 * CC) + 2 * CC + d] : 0.0f;
    }

    int warp = tid >> 5, lane = tid & 31;
    for (int i = warp; i < NN; i += AWARPS) {
        int li = labs[i];
        float sum = 0.0f;
        for (int j = lane; j < NN; j += 32) {
            float ev = (labs[j] == li) ? __expf(S[i * SST + j]) : 0.0f;
            S[i * SST + j] = ev;
            sum += ev;
        }
        #pragma unroll
        for (int o = 16; o; o >>= 1) sum += __shfl_xor_sync(0xffffffffu, sum, o);
        if (lane == 0) rsinv[i] = 1.0f / sum;
    }
    __syncthreads();

    for (int u = tid; u < 200; u += ATHREADS) {
        int it = u >> 3, dt = u & 7;
        int i0 = it * 4, d0 = dt * 4;
        float o[4][4];
        #pragma unroll
        for (int a = 0; a < 4; a++)
            #pragma unroll
            for (int b = 0; b < 4; b++) o[a][b] = 0.0f;
        #pragma unroll 5
        for (int jc = 0; jc < 25; jc++) {
            int j0 = jc * 4;
            float4 p[4], vv[4];
            #pragma unroll
            for (int a = 0; a < 4; a++)
                p[a] = *(const float4*)&S[(i0 + a) * SST + j0];
            #pragma unroll
            for (int b = 0; b < 4; b++)
                vv[b] = *(const float4*)&v[(j0 + b) * VSTR + d0];
            #pragma unroll
            for (int a = 0; a < 4; a++) {
                o[a][0] = fmaf(p[a].x, vv[0].x, o[a][0]);
                o[a][1] = fmaf(p[a].x, vv[0].y, o[a][1]);
                o[a][2] = fmaf(p[a].x, vv[0].z, o[a][2]);
                o[a][3] = fmaf(p[a].x, vv[0].w, o[a][3]);
                o[a][0] = fmaf(p[a].y, vv[1].x, o[a][0]);
                o[a][1] = fmaf(p[a].y, vv[1].y, o[a][1]);
                o[a][2] = fmaf(p[a].y, vv[1].z, o[a][2]);
                o[a][3] = fmaf(p[a].y, vv[1].w, o[a][3]);
                o[a][0] = fmaf(p[a].z, vv[2].x, o[a][0]);
                o[a][1] = fmaf(p[a].z, vv[2].y, o[a][1]);
                o[a][2] = fmaf(p[a].z, vv[2].z, o[a][2]);
                o[a][3] = fmaf(p[a].z, vv[2].w, o[a][3]);
                o[a][0] = fmaf(p[a].w, vv[3].x, o[a][0]);
                o[a][1] = fmaf(p[a].w, vv[3].y, o[a][1]);
                o[a][2] = fmaf(p[a].w, vv[3].z, o[a][2]);
                o[a][3] = fmaf(p[a].w, vv[3].w, o[a][3]);
            }
        }
        size_t ob = (size_t)(win * NN) * CC + head * HD + d0;
        #pragma unroll
        for (int a = 0; a < 4; a++) {
            int i = i0 + a;
            if (i < NN) {
                float rs = rsinv[i];
                *(float4*)&out[ob + (size_t)i * CC] =
                    make_float4(round_tf32(o[a][0] * rs), round_tf32(o[a][1] * rs),
                                round_tf32(o[a][2] * rs), round_tf32(o[a][3] * rs));
            }
        }
    }
}

// ---------------- launch ----------------
extern "C" void kernel_launch(void* const* d_in, const int* in_sizes, int n_in,
                              void* d_out, int out_size) {
    const float* x      = (const float*)d_in[0];
    // d_in[1] = mask_matrix (unused: mask computed analytically)
    const float* n1g    = (const float*)d_in[2];
    const float* n1b    = (const float*)d_in[3];
    const float* qkv_w  = (const float*)d_in[4];
    const float* qkv_b  = (const float*)d_in[5];
    const float* proj_w = (const float*)d_in[6];
    const float* proj_b = (const float*)d_in[7];
    const float* n2g    = (const float*)d_in[8];
    const float* n2b    = (const float*)d_in[9];
    const float* fc1_w  = (const float*)d_in[10];
    const float* fc1_b  = (const float*)d_in[11];
    const float* fc2_w  = (const float*)d_in[12];
    const float* fc2_b  = (const float*)d_in[13];
    float* out = (float*)d_out;

    float *xw, *qkvb, *ao, *x1, *h2, *hid, *wr;
    cudaGetSymbolAddress((void**)&xw,   g_xw);
    cudaGetSymbolAddress((void**)&qkvb, g_qkv);
    cudaGetSymbolAddress((void**)&ao,   g_ao);
    cudaGetSymbolAddress((void**)&x1,   g_x1);
    cudaGetSymbolAddress((void**)&h2,   g_h2);
    cudaGetSymbolAddress((void**)&hid,  g_hid);
    cudaGetSymbolAddress((void**)&wr,   g_wr);

    cudaFuncSetAttribute(attn_kernel, cudaFuncAttributeMaxDynamicSharedMemorySize,
                         ATTN_SMEM);
    cudaFuncSetAttribute(gemm_kernel<0>, cudaFuncAttributeMaxDynamicSharedMemorySize,
                         GEMM_SMEM);
    cudaFuncSetAttribute(gemm_kernel<1>, cudaFuncAttributeMaxDynamicSharedMemorySize,
                         GEMM_SMEM);
    cudaFuncSetAttribute(gemm_kernel<2>, cudaFuncAttributeMaxDynamicSharedMemorySize,
                         GEMM_SMEM);
    cudaFuncSetAttribute(gemm_kernel<3>, cudaFuncAttributeMaxDynamicSharedMemorySize,
                         GEMM_SMEM);

    const int mtiles = TT / GBM;   // 1568

    // 0) round weights to tf32 (tiny)
    round_weights_kernel<<<(WTOT + 255) / 256, 256>>>(qkv_w, proj_w, fc1_w, fc2_w, wr);
    // 1) LN1 + shift + window partition (tf32-rounded out)
    ln_kernel<<<TT / 4, 128>>>(x, n1g, n1b, xw, 1);
    // 2) qkv = xw @ qkv_w^T + qkv_b   (Nd=288 = 3x96)
    gemm_kernel<0><<<dim3(3, mtiles), 256, GEMM_SMEM>>>(xw, wr + WQKV_OFF, qkv_b,
                                                        qkvb, nullptr, TT, 3 * CC, CC);
    // 3) windowed attention (single-pass softmax, deferred norm, 320 thr)
    attn_kernel<<<BW * HEADS, ATHREADS, ATTN_SMEM>>>(qkvb, ao);
    // 4) proj + window reverse + unshift + residual(x) -> x1  (Nd=96 = 1x96)
    gemm_kernel<1><<<dim3(1, mtiles), 256, GEMM_SMEM>>>(ao, wr + WPROJ_OFF, proj_b,
                                                        x1, x, TT, CC, CC);
    // 5) LN2 (tf32-rounded out)
    ln_kernel<<<TT / 4, 128>>>(x1, n2g, n2b, h2, 0);
    // 6) fc1 + exact GELU (Nd=384 = 4x96)
    gemm_kernel<2><<<dim3(4, mtiles), 256, GEMM_SMEM>>>(h2, wr + WFC1_OFF, fc1_b,
                                                        hid, nullptr, TT, HID, CC);
    // 7) fc2 + residual(x1) -> out  (Nd=96 = 1x96, K=384)
    gemm_kernel<3><<<dim3(1, mtiles), 256, GEMM_SMEM>>>(hid, wr + WFC2_OFF, fc2_b,
                                                        out, x1, TT, CC, HID);
}